// round 12
// baseline (speedup 1.0000x reference)
#include <cuda_runtime.h>
#include <cuda_bf16.h>
#include <cstdint>
#include <cmath>

#define B_   8
#define LQ   1024
#define LK   8192
#define D_   256
#define DC   128
#define EPSF 1e-6f
#define LN2F 0.69314718055994531f

// ---------------- scratch (no allocations allowed) ----------------
__device__ uint8_t        g_qt8[B_ * LQ * DC];    // q~ = q @ W_up, e4m3 (1 MB)
__device__ float          g_qsq[B_ * LQ];
__device__ uint8_t        g_kc8[B_ * LK * DC];    // dequantized codes, e4m3 (8 MB)
__device__ float          g_ksq[B_ * LK];
__device__ __nv_bfloat16  g_G[DC * DC];           // G = W^T W (bf16)

// ---------------- fast math ----------------
__device__ __forceinline__ float fast_rcp(float x)  { float r; asm("rcp.approx.f32 %0, %1;"  : "=f"(r) : "f"(x)); return r; }
__device__ __forceinline__ float fast_sqrt(float x) { float r; asm("sqrt.approx.f32 %0, %1;" : "=f"(r) : "f"(x)); return r; }
__device__ __forceinline__ float fast_lg2(float x)  { float r; asm("lg2.approx.f32 %0, %1;"  : "=f"(r) : "f"(x)); return r; }
__device__ __forceinline__ uint16_t pack_e4m3x2(float lo, float hi) {
    uint16_t u;
    asm("cvt.rn.satfinite.e4m3x2.f32 %0, %1, %2;" : "=h"(u) : "f"(hi), "f"(lo));
    return u;
}

// ---------------- mma helpers ----------------
__device__ __forceinline__ uint32_t sptr(const void* p) {
    return (uint32_t)__cvta_generic_to_shared(p);
}
__device__ __forceinline__ void ldsm4(uint32_t& a0, uint32_t& a1, uint32_t& a2, uint32_t& a3, uint32_t addr) {
    asm volatile("ldmatrix.sync.aligned.m8n8.x4.shared.b16 {%0,%1,%2,%3}, [%4];"
                 : "=r"(a0), "=r"(a1), "=r"(a2), "=r"(a3) : "r"(addr));
}
__device__ __forceinline__ void ldsm2(uint32_t& b0, uint32_t& b1, uint32_t addr) {
    asm volatile("ldmatrix.sync.aligned.m8n8.x2.shared.b16 {%0,%1}, [%2];"
                 : "=r"(b0), "=r"(b1) : "r"(addr));
}
__device__ __forceinline__ void mma16816(float& c0, float& c1, float& c2, float& c3,
                                         uint32_t a0, uint32_t a1, uint32_t a2, uint32_t a3,
                                         uint32_t b0, uint32_t b1) {
    asm volatile("mma.sync.aligned.m16n8k16.row.col.f32.bf16.bf16.f32 "
                 "{%0,%1,%2,%3}, {%4,%5,%6,%7}, {%8,%9}, {%0,%1,%2,%3};"
                 : "+f"(c0), "+f"(c1), "+f"(c2), "+f"(c3)
                 : "r"(a0), "r"(a1), "r"(a2), "r"(a3), "r"(b0), "r"(b1));
}
__device__ __forceinline__ void mma16832fp8(float& c0, float& c1, float& c2, float& c3,
                                            uint32_t a0, uint32_t a1, uint32_t a2, uint32_t a3,
                                            uint32_t b0, uint32_t b1) {
    asm volatile("mma.sync.aligned.m16n8k32.row.col.f32.e4m3.e4m3.f32 "
                 "{%0,%1,%2,%3}, {%4,%5,%6,%7}, {%8,%9}, {%0,%1,%2,%3};"
                 : "+f"(c0), "+f"(c1), "+f"(c2), "+f"(c3)
                 : "r"(a0), "r"(a1), "r"(a2), "r"(a3), "r"(b0), "r"(b1));
}
__device__ __forceinline__ void cp16(uint32_t dst, const void* src) {
    asm volatile("cp.async.cg.shared.global [%0], [%1], 16;" :: "r"(dst), "l"(src));
}
__device__ __forceinline__ void cp_commit() { asm volatile("cp.async.commit_group;" ::: "memory"); }
__device__ __forceinline__ void cp_wait0()  { asm volatile("cp.async.wait_group 0;" ::: "memory"); }

// ---------------- kernel 1: MERGED  G = W^T W  +  q~ = q @ W (+ q_sq) ----------------
// blocks [0,128): G;  blocks [128,256): prepq (64 q-rows each, builds W^T locally)
#define QR 64
#define QSTRIDE 264
#define SMEM_PREP1 (QR * QSTRIDE * 2 + 128 * QSTRIDE * 2 + 128 * 4 + QR * 4 + 256)

__global__ void k_prep1(const float* __restrict__ W, const float* __restrict__ q) {
    extern __shared__ char sm[];
    const int t = threadIdx.x;                    // 256

    if (blockIdx.x < 128) {
        // ---- G part: G[c1][c2] = sum_d W[d][c1] W[d][c2] ----
        float* col = (float*)sm;                  // [256]
        float* red = col + 256;                   // [256]
        const int c1 = blockIdx.x;
        const int c2 = t & 127, h = t >> 7;

        col[t] = W[t * DC + c1];
        __syncthreads();

        float acc = 0.f;
        const int d0 = h * 128;
        #pragma unroll 8
        for (int d = 0; d < 128; d++) acc += col[d0 + d] * W[(d0 + d) * DC + c2];
        red[t] = acc;
        __syncthreads();
        if (h == 0) g_G[c1 * DC + c2] = __float2bfloat16(red[c2] + red[c2 + 128]);
        return;
    }

    // ---- prepq part ----
    __nv_bfloat16* qs  = (__nv_bfloat16*)sm;                 // [64][264]
    __nv_bfloat16* Wts = qs + QR * QSTRIDE;                  // [128][264] = W^T
    float*         par = (float*)(Wts + 128 * QSTRIDE);      // [128]
    float*         qsq = par + 128;                          // [64]

    const int r0 = (blockIdx.x - 128) * QR;

    // build W^T bf16 tile straight from W (transpose through smem)
    {
        const float4* Wv = (const float4*)W;      // 8192 float4
        #pragma unroll
        for (int i = 0; i < 32; i++) {
            int idx4 = t + i * 256;
            int d = idx4 >> 5, c4 = (idx4 & 31) * 4;
            float4 v = Wv[idx4];
            Wts[(c4 + 0) * QSTRIDE + d] = __float2bfloat16(v.x);
            Wts[(c4 + 1) * QSTRIDE + d] = __float2bfloat16(v.y);
            Wts[(c4 + 2) * QSTRIDE + d] = __float2bfloat16(v.z);
            Wts[(c4 + 3) * QSTRIDE + d] = __float2bfloat16(v.w);
        }
    }
    // q tile (64 x 256 fp32) -> bf16 smem
    {
        const float4* src = (const float4*)(q + (size_t)r0 * D_);
        #pragma unroll
        for (int i = 0; i < 16; i++) {
            int idx = t + i * 256;
            int row = idx >> 6, c4 = (idx & 63) * 4;
            float4 v = src[idx];
            *(__nv_bfloat162*)&qs[row * QSTRIDE + c4]     = __floats2bfloat162_rn(v.x, v.y);
            *(__nv_bfloat162*)&qs[row * QSTRIDE + c4 + 2] = __floats2bfloat162_rn(v.z, v.w);
        }
    }
    // q_sq in fp32: 2 threads per row
    if (t < 128) {
        const float4* rowp = (const float4*)(q + (size_t)(r0 + (t >> 1)) * D_) + (t & 1) * 32;
        float ss = 0.f;
        #pragma unroll 8
        for (int i = 0; i < 32; i++) {
            float4 v = rowp[i];
            ss += v.x * v.x + v.y * v.y + v.z * v.z + v.w * v.w;
        }
        par[t] = ss;
    }
    __syncthreads();
    if (t < QR) qsq[t] = par[2 * t] + par[2 * t + 1];

    const int w = t >> 5, lane = t & 31;
    const int m0 = (w >> 2) * 32, n0 = (w & 3) * 32;
    const int gid = lane >> 2, tid2 = lane & 3;
    const int arow = lane & 15, acol = ((lane >> 4) << 3);
    const int brow = lane & 7,  bcol = (((lane >> 3) & 1) << 3);

    float acc[2][4][4];
    #pragma unroll
    for (int i = 0; i < 2; i++)
        #pragma unroll
        for (int j = 0; j < 4; j++)
            #pragma unroll
            for (int c = 0; c < 4; c++) acc[i][j][c] = 0.f;

    #pragma unroll
    for (int ks = 0; ks < 16; ks++) {
        const int k0 = ks * 16;
        uint32_t A[2][4], Bf[4][2];
        #pragma unroll
        for (int ms = 0; ms < 2; ms++)
            ldsm4(A[ms][0], A[ms][1], A[ms][2], A[ms][3],
                  sptr(&qs[(m0 + ms * 16 + arow) * QSTRIDE + k0 + acol]));
        #pragma unroll
        for (int ns = 0; ns < 4; ns++)
            ldsm2(Bf[ns][0], Bf[ns][1],
                  sptr(&Wts[(n0 + ns * 8 + brow) * QSTRIDE + k0 + bcol]));
        #pragma unroll
        for (int ms = 0; ms < 2; ms++)
            #pragma unroll
            for (int ns = 0; ns < 4; ns++)
                mma16816(acc[ms][ns][0], acc[ms][ns][1], acc[ms][ns][2], acc[ms][ns][3],
                         A[ms][0], A[ms][1], A[ms][2], A[ms][3], Bf[ns][0], Bf[ns][1]);
    }

    #pragma unroll
    for (int ms = 0; ms < 2; ms++) {
        const int rA = m0 + ms * 16 + gid, rB = rA + 8;
        #pragma unroll
        for (int ns = 0; ns < 4; ns++) {
            const int c0 = n0 + ns * 8 + tid2 * 2;
            *(uint16_t*)&g_qt8[(size_t)(r0 + rA) * DC + c0] = pack_e4m3x2(acc[ms][ns][0], acc[ms][ns][1]);
            *(uint16_t*)&g_qt8[(size_t)(r0 + rB) * DC + c0] = pack_e4m3x2(acc[ms][ns][2], acc[ms][ns][3]);
        }
    }
    __syncthreads();
    if (t < QR) g_qsq[r0 + t] = qsq[t];
}

// ---------------- kernel 2: dequant codes + k_sq = kc^T G kc (64 rows/block) ----------------
#define PSTRIDE 136
#define SMEM_PREPK (64 * PSTRIDE * 2 + 128 * PSTRIDE * 2 + 64 * 4 + 256)

__global__ void k_prepk(const int* __restrict__ kq,
                        const float* __restrict__ kscale,
                        const float* __restrict__ kzero) {
    extern __shared__ char sm[];
    __nv_bfloat16* kcs  = (__nv_bfloat16*)sm;                 // [64][136]
    __nv_bfloat16* Gs   = kcs + 64 * PSTRIDE;                 // [128][136]
    float*         ksqs = (float*)(Gs + 128 * PSTRIDE);       // [64]

    const int t    = threadIdx.x;        // 256
    const int row0 = blockIdx.x * 64;    // 1024 blocks
    const int b    = row0 / LK;

    // dequant 64 x 128 codes -> bf16 smem + e4m3 global
    {
        const int c4 = (t & 31) * 4;
        const float4 sc = *(const float4*)(kscale + b * DC + c4);
        const float4 zr = *(const float4*)(kzero + b * DC + c4);
        const int rb = t >> 5;           // 0..7
        #pragma unroll
        for (int i = 0; i < 8; i++) {
            const int r = rb + i * 8;
            const int4 code = *(const int4*)(kq + (size_t)(row0 + r) * DC + c4);
            float v0 = sc.x * ((float)code.x - zr.x);
            float v1 = sc.y * ((float)code.y - zr.y);
            float v2 = sc.z * ((float)code.z - zr.z);
            float v3 = sc.w * ((float)code.w - zr.w);
            __nv_bfloat162 p0, p1;
            p0.x = __float2bfloat16(v0); p0.y = __float2bfloat16(v1);
            p1.x = __float2bfloat16(v2); p1.y = __float2bfloat16(v3);
            *(__nv_bfloat162*)&kcs[r * PSTRIDE + c4]     = p0;
            *(__nv_bfloat162*)&kcs[r * PSTRIDE + c4 + 2] = p1;
            uint32_t pk = (uint32_t)pack_e4m3x2(v0, v1) | ((uint32_t)pack_e4m3x2(v2, v3) << 16);
            *(uint32_t*)&g_kc8[(size_t)(row0 + r) * DC + c4] = pk;
        }
    }
    // load G (34816B)
    {
        const int r = t >> 1, ch = (t & 1) * 64;
        const uint4* src = (const uint4*)(g_G + r * DC + ch);
        #pragma unroll
        for (int i = 0; i < 8; i++) *(uint4*)&Gs[r * PSTRIDE + ch + i * 8] = src[i];
    }
    if (t < 64) ksqs[t] = 0.f;
    __syncthreads();

    const int w = t >> 5, lane = t & 31;
    const int m0 = (w >> 2) * 32, n0 = (w & 3) * 32;
    const int gid = lane >> 2, tid2 = lane & 3;
    const int arow = lane & 15, acol = ((lane >> 4) << 3);
    const int brow = lane & 7,  bcol = (((lane >> 3) & 1) << 3);

    float acc[2][4][4];
    #pragma unroll
    for (int i = 0; i < 2; i++)
        #pragma unroll
        for (int j = 0; j < 4; j++)
            #pragma unroll
            for (int c = 0; c < 4; c++) acc[i][j][c] = 0.f;

    #pragma unroll
    for (int ks = 0; ks < 8; ks++) {
        const int k0 = ks * 16;
        uint32_t A[2][4], Bf[4][2];
        #pragma unroll
        for (int ms = 0; ms < 2; ms++)
            ldsm4(A[ms][0], A[ms][1], A[ms][2], A[ms][3],
                  sptr(&kcs[(m0 + ms * 16 + arow) * PSTRIDE + k0 + acol]));
        #pragma unroll
        for (int ns = 0; ns < 4; ns++)
            ldsm2(Bf[ns][0], Bf[ns][1],
                  sptr(&Gs[(n0 + ns * 8 + brow) * PSTRIDE + k0 + bcol]));
        #pragma unroll
        for (int ms = 0; ms < 2; ms++)
            #pragma unroll
            for (int ns = 0; ns < 4; ns++)
                mma16816(acc[ms][ns][0], acc[ms][ns][1], acc[ms][ns][2], acc[ms][ns][3],
                         A[ms][0], A[ms][1], A[ms][2], A[ms][3], Bf[ns][0], Bf[ns][1]);
    }

    #pragma unroll
    for (int ms = 0; ms < 2; ms++) {
        const int rA = m0 + ms * 16 + gid, rB = rA + 8;
        float sA = 0.f, sB = 0.f;
        #pragma unroll
        for (int ns = 0; ns < 4; ns++) {
            const int c0 = n0 + ns * 8 + tid2 * 2;
            sA += acc[ms][ns][0] * __bfloat162float(kcs[rA * PSTRIDE + c0]);
            sA += acc[ms][ns][1] * __bfloat162float(kcs[rA * PSTRIDE + c0 + 1]);
            sB += acc[ms][ns][2] * __bfloat162float(kcs[rB * PSTRIDE + c0]);
            sB += acc[ms][ns][3] * __bfloat162float(kcs[rB * PSTRIDE + c0 + 1]);
        }
        atomicAdd(&ksqs[rA], sA);
        atomicAdd(&ksqs[rB], sB);
    }
    __syncthreads();
    if (t < 64) g_ksq[row0 + t] = ksqs[t];
}

// ---------------- kernel 3: main — FP8 MMA, 128x64 tile (unchanged hot path) ----------------
#define KB 4
#define KT 64
#define PS8 144
#define QT8_BYTES (128 * PS8)
#define KT8_BYTES (KT * PS8)
#define SM_KT8    QT8_BYTES
#define SM_NRM    (QT8_BYTES + 2 * KT8_BYTES)
#define SMEM_MAIN (SM_NRM + 2 * 128 * 4 + 2 * KT * 4 + 256)

__global__ void __launch_bounds__(256, 3) k_main(float* __restrict__ out) {
    extern __shared__ char sm[];
    uint8_t* qts  = (uint8_t*)sm;                      // [128][144] e4m3
    uint8_t* kcs  = (uint8_t*)sm + SM_KT8;             // [2][64][144] e4m3, rows permuted
    float*   qsqs = (float*)(sm + SM_NRM);             // [128]
    float*   rqs  = qsqs + 128;                        // [128]
    float*   ksqr = rqs + 128;                         // [2][64]

    const int t = threadIdx.x;                         // 256
    const int kbb = blockIdx.x, qb = blockIdx.y, b = blockIdx.z;
    const int q0 = qb * 128, kbase = kbb * (KT * KB);

    {
        const int rq = t >> 1, chb = (t & 1) * 64;
        const uint4* s1 = (const uint4*)(g_qt8 + ((size_t)(b * LQ + q0 + rq)) * DC + chb);
        #pragma unroll
        for (int i = 0; i < 4; i++) *(uint4*)(qts + rq * PS8 + chb + i * 16) = s1[i];
    }
    if (t < 128) {
        float qs = g_qsq[b * LQ + q0 + t];
        qsqs[t] = qs;
        rqs[t] = 1.f - fminf(qs, 1.f - EPSF);
    }

    const int rk = t >> 2, kchb = (t & 3) * 32;
    const int lk_ = rk & 15;
    const int prk = (rk & ~15) | (((lk_ >> 1) & 1) * 8 + ((lk_ >> 2) << 1) + (lk_ & 1));

    {
        const uint32_t dst = sptr(kcs + prk * PS8 + kchb);
        const char* src = (const char*)(g_kc8 + ((size_t)(b * LK + kbase + rk)) * DC + kchb);
        cp16(dst, src);
        cp16(dst + 16, src + 16);
        if (t < 16) cp16(sptr(&ksqr[t * 4]), g_ksq + b * LK + kbase + t * 4);
    }
    cp_commit();

    const int w = t >> 5, lane = t & 31;
    const int m0 = (w & 3) * 32, nw0 = (w >> 2) * 32;
    const int gid = lane >> 2, tid2 = lane & 3;
    const int arow = lane & 15, acolb = ((lane >> 4) << 4);
    const int brow16 = (lane & 7) + ((lane >> 4) << 3);
    const int bcolb = (((lane >> 3) & 1) << 4);

    const float N0C = EPSF + EPSF * EPSF;
    const float H0  = 0.5f * N0C;
    const float C0  = LN2F * (2.f - fast_lg2(N0C));
    const float TH  = 50.5f * N0C;
    const float I2N = 2.f * fast_rcp(N0C);

    __syncthreads();

    const int rowA0 = m0 + gid, rowA1 = m0 + 16 + gid;
    float aA[2], aB[2];
    aA[0] = qsqs[rowA0] + H0;      aB[0] = qsqs[rowA0 + 8] + H0;
    aA[1] = qsqs[rowA1] + H0;      aB[1] = qsqs[rowA1 + 8] + H0;
    bool uniQ = (aA[0] >= 1.f) & (aB[0] >= 1.f) & (aA[1] >= 1.f) & (aB[1] >= 1.f);
    float* pA0 = out + ((size_t)(b * LQ + q0 + rowA0)) * LK + kbase + nw0 + 4 * tid2;
    float* pB0 = pA0 + (size_t)8 * LK;
    float* pA1 = out + ((size_t)(b * LQ + q0 + rowA1)) * LK + kbase + nw0 + 4 * tid2;
    float* pB1 = pA1 + (size_t)8 * LK;

    for (int kb = 0; kb < KB; kb++) {
        cp_wait0();
        __syncthreads();

        const float* kraw = ksqr + (kb & 1) * KT;
        float4 ks4[2];
        ks4[0] = *(const float4*)&kraw[nw0 + 4 * tid2];
        ks4[1] = *(const float4*)&kraw[nw0 + 16 + 4 * tid2];

        if (kb + 1 < KB) {
            const int nb = (kb + 1) & 1;
            const uint32_t dst = sptr(kcs + nb * KT8_BYTES + prk * PS8 + kchb);
            const char* src = (const char*)(g_kc8 + ((size_t)(b * LK + kbase + (kb + 1) * KT + rk)) * DC + kchb);
            cp16(dst, src);
            cp16(dst + 16, src + 16);
            if (t < 16) cp16(sptr(&ksqr[nb * KT + t * 4]),
                             g_ksq + b * LK + kbase + (kb + 1) * KT + t * 4);
            cp_commit();
        }

        const uint8_t* kbuf = kcs + (kb & 1) * KT8_BYTES;

        float acc[2][4][4];
        #pragma unroll
        for (int i = 0; i < 2; i++)
            #pragma unroll
            for (int j = 0; j < 4; j++)
                #pragma unroll
                for (int c = 0; c < 4; c++) acc[i][j][c] = 0.f;

        #pragma unroll
        for (int ks = 0; ks < 4; ks++) {
            const int k0b = ks * 32;
            uint32_t A[2][4], Bf[2][4];
            #pragma unroll
            for (int ms = 0; ms < 2; ms++)
                ldsm4(A[ms][0], A[ms][1], A[ms][2], A[ms][3],
                      sptr(qts + (m0 + ms * 16 + arow) * PS8 + k0b + acolb));
            #pragma unroll
            for (int P = 0; P < 2; P++)
                ldsm4(Bf[P][0], Bf[P][1], Bf[P][2], Bf[P][3],
                      sptr(kbuf + (nw0 + P * 16 + brow16) * PS8 + k0b + bcolb));
            #pragma unroll
            for (int ms = 0; ms < 2; ms++)
                #pragma unroll
                for (int P = 0; P < 2; P++) {
                    mma16832fp8(acc[ms][2*P][0], acc[ms][2*P][1], acc[ms][2*P][2], acc[ms][2*P][3],
                                A[ms][0], A[ms][1], A[ms][2], A[ms][3], Bf[P][0], Bf[P][1]);
                    mma16832fp8(acc[ms][2*P+1][0], acc[ms][2*P+1][1], acc[ms][2*P+1][2], acc[ms][2*P+1][3],
                                A[ms][0], A[ms][1], A[ms][2], A[ms][3], Bf[P][2], Bf[P][3]);
                }
        }

        bool uni = uniQ &&
                   ks4[0].x >= 1.f - EPSF && ks4[0].y >= 1.f - EPSF &&
                   ks4[0].z >= 1.f - EPSF && ks4[0].w >= 1.f - EPSF &&
                   ks4[1].x >= 1.f - EPSF && ks4[1].y >= 1.f - EPSF &&
                   ks4[1].z >= 1.f - EPSF && ks4[1].w >= 1.f - EPSF;

        if (uni) {
            #pragma unroll
            for (int ms = 0; ms < 2; ms++) {
                float* pA = ms ? pA1 : pA0;
                float* pB = ms ? pB1 : pB0;
                #pragma unroll
                for (int P = 0; P < 2; P++) {
                    const float4 kk = ks4[P];
                    const float ksv[4] = { kk.x, kk.y, kk.z, kk.w };
                    float vA[4] = { acc[ms][2*P][0], acc[ms][2*P][1], acc[ms][2*P+1][0], acc[ms][2*P+1][1] };
                    float vB[4] = { acc[ms][2*P][2], acc[ms][2*P][3], acc[ms][2*P+1][2], acc[ms][2*P+1][3] };

                    float xA[4], xB[4], dA[4], dB[4];
                    bool bad = false;
                    #pragma unroll
                    for (int j = 0; j < 4; j++) {
                        xA[j] = fmaxf(fmaf(-2.f, vA[j], aA[ms] + ksv[j]), H0);
                        xB[j] = fmaxf(fmaf(-2.f, vB[j], aB[ms] + ksv[j]), H0);
                        bad |= (xA[j] < TH) | (xB[j] < TH);
                        dA[j] = fmaf(fast_lg2(xA[j]), LN2F, C0);
                        dB[j] = fmaf(fast_lg2(xB[j]), LN2F, C0);
                    }
                    if (bad) {
                        #pragma unroll
                        for (int j = 0; j < 4; j++) {
                            float tA = (xA[j] - H0) * I2N;
                            float sA = fast_sqrt(fmaf(tA, tA, 2.f * tA));
                            dA[j] = LN2F * fast_lg2(1.f + tA + sA);
                            float tB = (xB[j] - H0) * I2N;
                            float sB = fast_sqrt(fmaf(tB, tB, 2.f * tB));
                            dB[j] = LN2F * fast_lg2(1.f + tB + sB);
                        }
                    }
                    __stcs((float4*)(pA + P * 16), make_float4(dA[0], dA[1], dA[2], dA[3]));
                    __stcs((float4*)(pB + P * 16), make_float4(dB[0], dB[1], dB[2], dB[3]));
                }
            }
        } else {
            #pragma unroll
            for (int ms = 0; ms < 2; ms++) {
                const int rA = m0 + ms * 16 + gid, rB = rA + 8;
                const float qsA = qsqs[rA], qsB = qsqs[rB];
                const float rqA = rqs[rA],  rqB = rqs[rB];
                float* pA = ms ? pA1 : pA0;
                float* pB = ms ? pB1 : pB0;
                #pragma unroll
                for (int P = 0; P < 2; P++) {
                    const float4 kk = ks4[P];
                    const float ksv[4] = { kk.x, kk.y, kk.z, kk.w };
                    float vA[4] = { acc[ms][2*P][0], acc[ms][2*P][1], acc[ms][2*P+1][0], acc[ms][2*P+1][1] };
                    float vB[4] = { acc[ms][2*P][2], acc[ms][2*P][3], acc[ms][2*P+1][2], acc[ms][2*P+1][3] };

                    float dA[4], dB[4];
                    #pragma unroll
                    for (int j = 0; j < 4; j++) {
                        const float rkj = 1.f - fminf(ksv[j], 1.f - EPSF);
                        float uA = 2.f * fmaxf(fmaf(-2.f, vA[j], qsA + ksv[j]), 0.f);
                        float nA = fmaf(rqA, rkj, EPSF);
                        float uB = 2.f * fmaxf(fmaf(-2.f, vB[j], qsB + ksv[j]), 0.f);
                        float nB = fmaf(rqB, rkj, EPSF);
                        if (uA >= 100.f * nA) {
                            dA[j] = LN2F * (1.f + fast_lg2(uA + nA) - fast_lg2(nA));
                        } else {
                            float tA = uA * fast_rcp(nA);
                            float sA = fast_sqrt(fmaf(tA, tA, 2.f * tA));
                            dA[j] = LN2F * fast_lg2(1.f + tA + sA);
                        }
                        if (uB >= 100.f * nB) {
                            dB[j] = LN2F * (1.f + fast_lg2(uB + nB) - fast_lg2(nB));
                        } else {
                            float tB = uB * fast_rcp(nB);
                            float sB = fast_sqrt(fmaf(tB, tB, 2.f * tB));
                            dB[j] = LN2F * fast_lg2(1.f + tB + sB);
                        }
                    }
                    __stcs((float4*)(pA + P * 16), make_float4(dA[0], dA[1], dA[2], dA[3]));
                    __stcs((float4*)(pB + P * 16), make_float4(dB[0], dB[1], dB[2], dB[3]));
                }
            }
        }
        pA0 += KT; pB0 += KT; pA1 += KT; pB1 += KT;
    }
}

// ---------------- launch ----------------
extern "C" void kernel_launch(void* const* d_in, const int* in_sizes, int n_in,
                              void* d_out, int out_size) {
    const float* q   = (const float*)d_in[0];
    const int*   kq  = (const int*)d_in[1];
    const float* ksc = (const float*)d_in[2];
    const float* kz  = (const float*)d_in[3];
    const float* W   = (const float*)d_in[4];
    float* out = (float*)d_out;
    (void)in_sizes; (void)n_in; (void)out_size;

    cudaFuncSetAttribute(k_prep1, cudaFuncAttributeMaxDynamicSharedMemorySize, SMEM_PREP1);
    cudaFuncSetAttribute(k_prepk, cudaFuncAttributeMaxDynamicSharedMemorySize, SMEM_PREPK);
    cudaFuncSetAttribute(k_main,  cudaFuncAttributeMaxDynamicSharedMemorySize, SMEM_MAIN);

    k_prep1<<<128 + (B_ * LQ) / QR, 256, SMEM_PREP1>>>(W, q);
    k_prepk<<<(B_ * LK) / 64, 256, SMEM_PREPK>>>(kq, ksc, kz);
    k_main<<<dim3(LK / (KT * KB), LQ / 128, B_), 256, SMEM_MAIN>>>(out);
}

// round 13
// speedup vs baseline: 1.1217x; 1.1217x over previous
#include <cuda_runtime.h>
#include <cuda_bf16.h>
#include <cstdint>
#include <cmath>

#define B_   8
#define LQ   1024
#define LK   8192
#define D_   256
#define DC   128
#define EPSF 1e-6f
#define LN2F 0.69314718055994531f

// ---------------- scratch (no allocations allowed) ----------------
__device__ uint8_t        g_qt8[B_ * LQ * DC];    // q~ = q @ W_up, e4m3 (1 MB)
__device__ float          g_qsq[B_ * LQ];
__device__ uint8_t        g_kc8[B_ * LK * DC];    // dequantized codes, e4m3 (8 MB)
__device__ float          g_ksq[B_ * LK];
__device__ __nv_bfloat16  g_G[DC * DC];           // G = W^T W (bf16)
__device__ __nv_bfloat16  g_Wt[DC * D_];          // W^T (c-major)

// ---------------- fast math ----------------
__device__ __forceinline__ float fast_rcp(float x)  { float r; asm("rcp.approx.f32 %0, %1;"  : "=f"(r) : "f"(x)); return r; }
__device__ __forceinline__ float fast_sqrt(float x) { float r; asm("sqrt.approx.f32 %0, %1;" : "=f"(r) : "f"(x)); return r; }
__device__ __forceinline__ float fast_lg2(float x)  { float r; asm("lg2.approx.f32 %0, %1;"  : "=f"(r) : "f"(x)); return r; }
__device__ __forceinline__ uint16_t pack_e4m3x2(float lo, float hi) {
    uint16_t u;
    asm("cvt.rn.satfinite.e4m3x2.f32 %0, %1, %2;" : "=h"(u) : "f"(hi), "f"(lo));
    return u;
}

// ---------------- mma helpers ----------------
__device__ __forceinline__ uint32_t sptr(const void* p) {
    return (uint32_t)__cvta_generic_to_shared(p);
}
__device__ __forceinline__ void ldsm4(uint32_t& a0, uint32_t& a1, uint32_t& a2, uint32_t& a3, uint32_t addr) {
    asm volatile("ldmatrix.sync.aligned.m8n8.x4.shared.b16 {%0,%1,%2,%3}, [%4];"
                 : "=r"(a0), "=r"(a1), "=r"(a2), "=r"(a3) : "r"(addr));
}
__device__ __forceinline__ void ldsm2(uint32_t& b0, uint32_t& b1, uint32_t addr) {
    asm volatile("ldmatrix.sync.aligned.m8n8.x2.shared.b16 {%0,%1}, [%2];"
                 : "=r"(b0), "=r"(b1) : "r"(addr));
}
__device__ __forceinline__ void mma16816(float& c0, float& c1, float& c2, float& c3,
                                         uint32_t a0, uint32_t a1, uint32_t a2, uint32_t a3,
                                         uint32_t b0, uint32_t b1) {
    asm volatile("mma.sync.aligned.m16n8k16.row.col.f32.bf16.bf16.f32 "
                 "{%0,%1,%2,%3}, {%4,%5,%6,%7}, {%8,%9}, {%0,%1,%2,%3};"
                 : "+f"(c0), "+f"(c1), "+f"(c2), "+f"(c3)
                 : "r"(a0), "r"(a1), "r"(a2), "r"(a3), "r"(b0), "r"(b1));
}
__device__ __forceinline__ void mma16832fp8(float& c0, float& c1, float& c2, float& c3,
                                            uint32_t a0, uint32_t a1, uint32_t a2, uint32_t a3,
                                            uint32_t b0, uint32_t b1) {
    asm volatile("mma.sync.aligned.m16n8k32.row.col.f32.e4m3.e4m3.f32 "
                 "{%0,%1,%2,%3}, {%4,%5,%6,%7}, {%8,%9}, {%0,%1,%2,%3};"
                 : "+f"(c0), "+f"(c1), "+f"(c2), "+f"(c3)
                 : "r"(a0), "r"(a1), "r"(a2), "r"(a3), "r"(b0), "r"(b1));
}
__device__ __forceinline__ void cp16(uint32_t dst, const void* src) {
    asm volatile("cp.async.cg.shared.global [%0], [%1], 16;" :: "r"(dst), "l"(src));
}
__device__ __forceinline__ void cp_commit() { asm volatile("cp.async.commit_group;" ::: "memory"); }
__device__ __forceinline__ void cp_wait0()  { asm volatile("cp.async.wait_group 0;" ::: "memory"); }

// ---------------- kernel 1: G = W^T W (bf16) + Wt bf16 (vectorized, conflict-free) ----------------
__global__ void k_G(const float* __restrict__ W) {
    __shared__ float col[D_];
    __shared__ float red[256];
    const int c1 = blockIdx.x;
    const int t  = threadIdx.x;
    const int c2 = t & 127, h = t >> 7;

    float wv = W[t * DC + c1];
    col[t] = wv;
    g_Wt[c1 * D_ + t] = __float2bfloat16(wv);
    __syncthreads();

    float acc = 0.f;
    const int d0 = h * 128;
    #pragma unroll 8
    for (int d = 0; d < 128; d++) acc += col[d0 + d] * W[(d0 + d) * DC + c2];
    red[t] = acc;
    __syncthreads();
    if (h == 0) g_G[c1 * DC + c2] = __float2bfloat16(red[c2] + red[c2 + 128]);
}

// ---------------- kernel 2: FUSED  prepq (blocks 0..127)  +  prepk (blocks 128..1151) ----------------
#define QR 64
#define QSTRIDE 264
#define PSTRIDE 136
#define SMEM_PREPQ (QR * QSTRIDE * 2 + 128 * QSTRIDE * 2 + 128 * 4 + QR * 4 + 256)
#define SMEM_PREPK (64 * PSTRIDE * 2 + 128 * PSTRIDE * 2 + 64 * 4 + 256)
#define SMEM_FUSED (SMEM_PREPQ > SMEM_PREPK ? SMEM_PREPQ : SMEM_PREPK)

__global__ void k_prep2(const float* __restrict__ q,
                        const int* __restrict__ kq,
                        const float* __restrict__ kscale,
                        const float* __restrict__ kzero) {
    extern __shared__ char sm[];
    const int t = threadIdx.x;                    // 256

    if (blockIdx.x < 128) {
        // ============ prepq: q~ = q @ W via MMA + q_sq ============
        __nv_bfloat16* qs  = (__nv_bfloat16*)sm;                 // [64][264]
        __nv_bfloat16* Wts = qs + QR * QSTRIDE;                  // [128][264]
        float*         par = (float*)(Wts + 128 * QSTRIDE);      // [128]
        float*         qsq = par + 128;                          // [64]

        const int r0 = blockIdx.x * QR;

        {
            const float4* src = (const float4*)(q + (size_t)r0 * D_);
            #pragma unroll
            for (int i = 0; i < 16; i++) {
                int idx = t + i * 256;
                int row = idx >> 6, c4 = (idx & 63) * 4;
                float4 v = src[idx];
                *(__nv_bfloat162*)&qs[row * QSTRIDE + c4]     = __floats2bfloat162_rn(v.x, v.y);
                *(__nv_bfloat162*)&qs[row * QSTRIDE + c4 + 2] = __floats2bfloat162_rn(v.z, v.w);
            }
        }
        if (t < 128) {
            const float4* rowp = (const float4*)(q + (size_t)(r0 + (t >> 1)) * D_) + (t & 1) * 32;
            float ss = 0.f;
            #pragma unroll 8
            for (int i = 0; i < 32; i++) {
                float4 v = rowp[i];
                ss += v.x * v.x + v.y * v.y + v.z * v.z + v.w * v.w;
            }
            par[t] = ss;
        }
        {
            #pragma unroll
            for (int i = 0; i < 16; i++) {
                int idx = t + i * 256;                 // 4096 uint4
                int r = idx >> 5, c8 = (idx & 31) * 8;
                *(uint4*)&Wts[r * QSTRIDE + c8] = ((const uint4*)g_Wt)[idx];
            }
        }
        __syncthreads();
        if (t < QR) qsq[t] = par[2 * t] + par[2 * t + 1];

        const int w = t >> 5, lane = t & 31;
        const int m0 = (w >> 2) * 32, n0 = (w & 3) * 32;
        const int gid = lane >> 2, tid2 = lane & 3;
        const int arow = lane & 15, acol = ((lane >> 4) << 3);
        const int brow = lane & 7,  bcol = (((lane >> 3) & 1) << 3);

        float acc[2][4][4];
        #pragma unroll
        for (int i = 0; i < 2; i++)
            #pragma unroll
            for (int j = 0; j < 4; j++)
                #pragma unroll
                for (int c = 0; c < 4; c++) acc[i][j][c] = 0.f;

        #pragma unroll
        for (int ks = 0; ks < 16; ks++) {
            const int k0 = ks * 16;
            uint32_t A[2][4], Bf[4][2];
            #pragma unroll
            for (int ms = 0; ms < 2; ms++)
                ldsm4(A[ms][0], A[ms][1], A[ms][2], A[ms][3],
                      sptr(&qs[(m0 + ms * 16 + arow) * QSTRIDE + k0 + acol]));
            #pragma unroll
            for (int ns = 0; ns < 4; ns++)
                ldsm2(Bf[ns][0], Bf[ns][1],
                      sptr(&Wts[(n0 + ns * 8 + brow) * QSTRIDE + k0 + bcol]));
            #pragma unroll
            for (int ms = 0; ms < 2; ms++)
                #pragma unroll
                for (int ns = 0; ns < 4; ns++)
                    mma16816(acc[ms][ns][0], acc[ms][ns][1], acc[ms][ns][2], acc[ms][ns][3],
                             A[ms][0], A[ms][1], A[ms][2], A[ms][3], Bf[ns][0], Bf[ns][1]);
        }

        #pragma unroll
        for (int ms = 0; ms < 2; ms++) {
            const int rA = m0 + ms * 16 + gid, rB = rA + 8;
            #pragma unroll
            for (int ns = 0; ns < 4; ns++) {
                const int c0 = n0 + ns * 8 + tid2 * 2;
                *(uint16_t*)&g_qt8[(size_t)(r0 + rA) * DC + c0] = pack_e4m3x2(acc[ms][ns][0], acc[ms][ns][1]);
                *(uint16_t*)&g_qt8[(size_t)(r0 + rB) * DC + c0] = pack_e4m3x2(acc[ms][ns][2], acc[ms][ns][3]);
            }
        }
        __syncthreads();
        if (t < QR) g_qsq[r0 + t] = qsq[t];
        return;
    }

    // ============ prepk: dequant codes + k_sq = kc^T G kc (64 rows/block) ============
    __nv_bfloat16* kcs  = (__nv_bfloat16*)sm;                 // [64][136]
    __nv_bfloat16* Gs   = kcs + 64 * PSTRIDE;                 // [128][136]
    float*         ksqs = (float*)(Gs + 128 * PSTRIDE);       // [64]

    const int row0 = (blockIdx.x - 128) * 64;    // 1024 blocks
    const int b    = row0 / LK;

    {
        const int c4 = (t & 31) * 4;
        const float4 sc = *(const float4*)(kscale + b * DC + c4);
        const float4 zr = *(const float4*)(kzero + b * DC + c4);
        const int rb = t >> 5;
        #pragma unroll
        for (int i = 0; i < 8; i++) {
            const int r = rb + i * 8;
            const int4 code = *(const int4*)(kq + (size_t)(row0 + r) * DC + c4);
            float v0 = sc.x * ((float)code.x - zr.x);
            float v1 = sc.y * ((float)code.y - zr.y);
            float v2 = sc.z * ((float)code.z - zr.z);
            float v3 = sc.w * ((float)code.w - zr.w);
            __nv_bfloat162 p0, p1;
            p0.x = __float2bfloat16(v0); p0.y = __float2bfloat16(v1);
            p1.x = __float2bfloat16(v2); p1.y = __float2bfloat16(v3);
            *(__nv_bfloat162*)&kcs[r * PSTRIDE + c4]     = p0;
            *(__nv_bfloat162*)&kcs[r * PSTRIDE + c4 + 2] = p1;
            uint32_t pk = (uint32_t)pack_e4m3x2(v0, v1) | ((uint32_t)pack_e4m3x2(v2, v3) << 16);
            *(uint32_t*)&g_kc8[(size_t)(row0 + r) * DC + c4] = pk;
        }
    }
    {
        const int r = t >> 1, ch = (t & 1) * 64;
        const uint4* src = (const uint4*)(g_G + r * DC + ch);
        #pragma unroll
        for (int i = 0; i < 8; i++) *(uint4*)&Gs[r * PSTRIDE + ch + i * 8] = src[i];
    }
    if (t < 64) ksqs[t] = 0.f;
    __syncthreads();

    const int w = t >> 5, lane = t & 31;
    const int m0 = (w >> 2) * 32, n0 = (w & 3) * 32;
    const int gid = lane >> 2, tid2 = lane & 3;
    const int arow = lane & 15, acol = ((lane >> 4) << 3);
    const int brow = lane & 7,  bcol = (((lane >> 3) & 1) << 3);

    float acc[2][4][4];
    #pragma unroll
    for (int i = 0; i < 2; i++)
        #pragma unroll
        for (int j = 0; j < 4; j++)
            #pragma unroll
            for (int c = 0; c < 4; c++) acc[i][j][c] = 0.f;

    #pragma unroll
    for (int ks = 0; ks < 8; ks++) {
        const int k0 = ks * 16;
        uint32_t A[2][4], Bf[4][2];
        #pragma unroll
        for (int ms = 0; ms < 2; ms++)
            ldsm4(A[ms][0], A[ms][1], A[ms][2], A[ms][3],
                  sptr(&kcs[(m0 + ms * 16 + arow) * PSTRIDE + k0 + acol]));
        #pragma unroll
        for (int ns = 0; ns < 4; ns++)
            ldsm2(Bf[ns][0], Bf[ns][1],
                  sptr(&Gs[(n0 + ns * 8 + brow) * PSTRIDE + k0 + bcol]));
        #pragma unroll
        for (int ms = 0; ms < 2; ms++)
            #pragma unroll
            for (int ns = 0; ns < 4; ns++)
                mma16816(acc[ms][ns][0], acc[ms][ns][1], acc[ms][ns][2], acc[ms][ns][3],
                         A[ms][0], A[ms][1], A[ms][2], A[ms][3], Bf[ns][0], Bf[ns][1]);
    }

    #pragma unroll
    for (int ms = 0; ms < 2; ms++) {
        const int rA = m0 + ms * 16 + gid, rB = rA + 8;
        float sA = 0.f, sB = 0.f;
        #pragma unroll
        for (int ns = 0; ns < 4; ns++) {
            const int c0 = n0 + ns * 8 + tid2 * 2;
            sA += acc[ms][ns][0] * __bfloat162float(kcs[rA * PSTRIDE + c0]);
            sA += acc[ms][ns][1] * __bfloat162float(kcs[rA * PSTRIDE + c0 + 1]);
            sB += acc[ms][ns][2] * __bfloat162float(kcs[rB * PSTRIDE + c0]);
            sB += acc[ms][ns][3] * __bfloat162float(kcs[rB * PSTRIDE + c0 + 1]);
        }
        atomicAdd(&ksqs[rA], sA);
        atomicAdd(&ksqs[rB], sB);
    }
    __syncthreads();
    if (t < 64) g_ksq[row0 + t] = ksqs[t];
}

// ---------------- kernel 3: main — FP8 MMA, 128x64 tile (unchanged, 90.6 us) ----------------
#define KB 4
#define KT 64
#define PS8 144
#define QT8_BYTES (128 * PS8)
#define KT8_BYTES (KT * PS8)
#define SM_KT8    QT8_BYTES
#define SM_NRM    (QT8_BYTES + 2 * KT8_BYTES)
#define SMEM_MAIN (SM_NRM + 2 * 128 * 4 + 2 * KT * 4 + 256)

__global__ void __launch_bounds__(256, 3) k_main(float* __restrict__ out) {
    extern __shared__ char sm[];
    uint8_t* qts  = (uint8_t*)sm;
    uint8_t* kcs  = (uint8_t*)sm + SM_KT8;
    float*   qsqs = (float*)(sm + SM_NRM);
    float*   rqs  = qsqs + 128;
    float*   ksqr = rqs + 128;

    const int t = threadIdx.x;
    const int kbb = blockIdx.x, qb = blockIdx.y, b = blockIdx.z;
    const int q0 = qb * 128, kbase = kbb * (KT * KB);

    {
        const int rq = t >> 1, chb = (t & 1) * 64;
        const uint4* s1 = (const uint4*)(g_qt8 + ((size_t)(b * LQ + q0 + rq)) * DC + chb);
        #pragma unroll
        for (int i = 0; i < 4; i++) *(uint4*)(qts + rq * PS8 + chb + i * 16) = s1[i];
    }
    if (t < 128) {
        float qs = g_qsq[b * LQ + q0 + t];
        qsqs[t] = qs;
        rqs[t] = 1.f - fminf(qs, 1.f - EPSF);
    }

    const int rk = t >> 2, kchb = (t & 3) * 32;
    const int lk_ = rk & 15;
    const int prk = (rk & ~15) | (((lk_ >> 1) & 1) * 8 + ((lk_ >> 2) << 1) + (lk_ & 1));

    {
        const uint32_t dst = sptr(kcs + prk * PS8 + kchb);
        const char* src = (const char*)(g_kc8 + ((size_t)(b * LK + kbase + rk)) * DC + kchb);
        cp16(dst, src);
        cp16(dst + 16, src + 16);
        if (t < 16) cp16(sptr(&ksqr[t * 4]), g_ksq + b * LK + kbase + t * 4);
    }
    cp_commit();

    const int w = t >> 5, lane = t & 31;
    const int m0 = (w & 3) * 32, nw0 = (w >> 2) * 32;
    const int gid = lane >> 2, tid2 = lane & 3;
    const int arow = lane & 15, acolb = ((lane >> 4) << 4);
    const int brow16 = (lane & 7) + ((lane >> 4) << 3);
    const int bcolb = (((lane >> 3) & 1) << 4);

    const float N0C = EPSF + EPSF * EPSF;
    const float H0  = 0.5f * N0C;
    const float C0  = LN2F * (2.f - fast_lg2(N0C));
    const float TH  = 50.5f * N0C;
    const float I2N = 2.f * fast_rcp(N0C);

    __syncthreads();

    const int rowA0 = m0 + gid, rowA1 = m0 + 16 + gid;
    float aA[2], aB[2];
    aA[0] = qsqs[rowA0] + H0;      aB[0] = qsqs[rowA0 + 8] + H0;
    aA[1] = qsqs[rowA1] + H0;      aB[1] = qsqs[rowA1 + 8] + H0;
    bool uniQ = (aA[0] >= 1.f) & (aB[0] >= 1.f) & (aA[1] >= 1.f) & (aB[1] >= 1.f);
    float* pA0 = out + ((size_t)(b * LQ + q0 + rowA0)) * LK + kbase + nw0 + 4 * tid2;
    float* pB0 = pA0 + (size_t)8 * LK;
    float* pA1 = out + ((size_t)(b * LQ + q0 + rowA1)) * LK + kbase + nw0 + 4 * tid2;
    float* pB1 = pA1 + (size_t)8 * LK;

    for (int kb = 0; kb < KB; kb++) {
        cp_wait0();
        __syncthreads();

        const float* kraw = ksqr + (kb & 1) * KT;
        float4 ks4[2];
        ks4[0] = *(const float4*)&kraw[nw0 + 4 * tid2];
        ks4[1] = *(const float4*)&kraw[nw0 + 16 + 4 * tid2];

        if (kb + 1 < KB) {
            const int nb = (kb + 1) & 1;
            const uint32_t dst = sptr(kcs + nb * KT8_BYTES + prk * PS8 + kchb);
            const char* src = (const char*)(g_kc8 + ((size_t)(b * LK + kbase + (kb + 1) * KT + rk)) * DC + kchb);
            cp16(dst, src);
            cp16(dst + 16, src + 16);
            if (t < 16) cp16(sptr(&ksqr[nb * KT + t * 4]),
                             g_ksq + b * LK + kbase + (kb + 1) * KT + t * 4);
            cp_commit();
        }

        const uint8_t* kbuf = kcs + (kb & 1) * KT8_BYTES;

        float acc[2][4][4];
        #pragma unroll
        for (int i = 0; i < 2; i++)
            #pragma unroll
            for (int j = 0; j < 4; j++)
                #pragma unroll
                for (int c = 0; c < 4; c++) acc[i][j][c] = 0.f;

        #pragma unroll
        for (int ks = 0; ks < 4; ks++) {
            const int k0b = ks * 32;
            uint32_t A[2][4], Bf[2][4];
            #pragma unroll
            for (int ms = 0; ms < 2; ms++)
                ldsm4(A[ms][0], A[ms][1], A[ms][2], A[ms][3],
                      sptr(qts + (m0 + ms * 16 + arow) * PS8 + k0b + acolb));
            #pragma unroll
            for (int P = 0; P < 2; P++)
                ldsm4(Bf[P][0], Bf[P][1], Bf[P][2], Bf[P][3],
                      sptr(kbuf + (nw0 + P * 16 + brow16) * PS8 + k0b + bcolb));
            #pragma unroll
            for (int ms = 0; ms < 2; ms++)
                #pragma unroll
                for (int P = 0; P < 2; P++) {
                    mma16832fp8(acc[ms][2*P][0], acc[ms][2*P][1], acc[ms][2*P][2], acc[ms][2*P][3],
                                A[ms][0], A[ms][1], A[ms][2], A[ms][3], Bf[P][0], Bf[P][1]);
                    mma16832fp8(acc[ms][2*P+1][0], acc[ms][2*P+1][1], acc[ms][2*P+1][2], acc[ms][2*P+1][3],
                                A[ms][0], A[ms][1], A[ms][2], A[ms][3], Bf[P][2], Bf[P][3]);
                }
        }

        bool uni = uniQ &&
                   ks4[0].x >= 1.f - EPSF && ks4[0].y >= 1.f - EPSF &&
                   ks4[0].z >= 1.f - EPSF && ks4[0].w >= 1.f - EPSF &&
                   ks4[1].x >= 1.f - EPSF && ks4[1].y >= 1.f - EPSF &&
                   ks4[1].z >= 1.f - EPSF && ks4[1].w >= 1.f - EPSF;

        if (uni) {
            #pragma unroll
            for (int ms = 0; ms < 2; ms++) {
                float* pA = ms ? pA1 : pA0;
                float* pB = ms ? pB1 : pB0;
                #pragma unroll
                for (int P = 0; P < 2; P++) {
                    const float4 kk = ks4[P];
                    const float ksv[4] = { kk.x, kk.y, kk.z, kk.w };
                    float vA[4] = { acc[ms][2*P][0], acc[ms][2*P][1], acc[ms][2*P+1][0], acc[ms][2*P+1][1] };
                    float vB[4] = { acc[ms][2*P][2], acc[ms][2*P][3], acc[ms][2*P+1][2], acc[ms][2*P+1][3] };

                    float xA[4], xB[4], dA[4], dB[4];
                    bool bad = false;
                    #pragma unroll
                    for (int j = 0; j < 4; j++) {
                        xA[j] = fmaxf(fmaf(-2.f, vA[j], aA[ms] + ksv[j]), H0);
                        xB[j] = fmaxf(fmaf(-2.f, vB[j], aB[ms] + ksv[j]), H0);
                        bad |= (xA[j] < TH) | (xB[j] < TH);
                        dA[j] = fmaf(fast_lg2(xA[j]), LN2F, C0);
                        dB[j] = fmaf(fast_lg2(xB[j]), LN2F, C0);
                    }
                    if (bad) {
                        #pragma unroll
                        for (int j = 0; j < 4; j++) {
                            float tA = (xA[j] - H0) * I2N;
                            float sA = fast_sqrt(fmaf(tA, tA, 2.f * tA));
                            dA[j] = LN2F * fast_lg2(1.f + tA + sA);
                            float tB = (xB[j] - H0) * I2N;
                            float sB = fast_sqrt(fmaf(tB, tB, 2.f * tB));
                            dB[j] = LN2F * fast_lg2(1.f + tB + sB);
                        }
                    }
                    __stcs((float4*)(pA + P * 16), make_float4(dA[0], dA[1], dA[2], dA[3]));
                    __stcs((float4*)(pB + P * 16), make_float4(dB[0], dB[1], dB[2], dB[3]));
                }
            }
        } else {
            #pragma unroll
            for (int ms = 0; ms < 2; ms++) {
                const int rA = m0 + ms * 16 + gid, rB = rA + 8;
                const float qsA = qsqs[rA], qsB = qsqs[rB];
                const float rqA = rqs[rA],  rqB = rqs[rB];
                float* pA = ms ? pA1 : pA0;
                float* pB = ms ? pB1 : pB0;
                #pragma unroll
                for (int P = 0; P < 2; P++) {
                    const float4 kk = ks4[P];
                    const float ksv[4] = { kk.x, kk.y, kk.z, kk.w };
                    float vA[4] = { acc[ms][2*P][0], acc[ms][2*P][1], acc[ms][2*P+1][0], acc[ms][2*P+1][1] };
                    float vB[4] = { acc[ms][2*P][2], acc[ms][2*P][3], acc[ms][2*P+1][2], acc[ms][2*P+1][3] };

                    float dA[4], dB[4];
                    #pragma unroll
                    for (int j = 0; j < 4; j++) {
                        const float rkj = 1.f - fminf(ksv[j], 1.f - EPSF);
                        float uA = 2.f * fmaxf(fmaf(-2.f, vA[j], qsA + ksv[j]), 0.f);
                        float nA = fmaf(rqA, rkj, EPSF);
                        float uB = 2.f * fmaxf(fmaf(-2.f, vB[j], qsB + ksv[j]), 0.f);
                        float nB = fmaf(rqB, rkj, EPSF);
                        if (uA >= 100.f * nA) {
                            dA[j] = LN2F * (1.f + fast_lg2(uA + nA) - fast_lg2(nA));
                        } else {
                            float tA = uA * fast_rcp(nA);
                            float sA = fast_sqrt(fmaf(tA, tA, 2.f * tA));
                            dA[j] = LN2F * fast_lg2(1.f + tA + sA);
                        }
                        if (uB >= 100.f * nB) {
                            dB[j] = LN2F * (1.f + fast_lg2(uB + nB) - fast_lg2(nB));
                        } else {
                            float tB = uB * fast_rcp(nB);
                            float sB = fast_sqrt(fmaf(tB, tB, 2.f * tB));
                            dB[j] = LN2F * fast_lg2(1.f + tB + sB);
                        }
                    }
                    __stcs((float4*)(pA + P * 16), make_float4(dA[0], dA[1], dA[2], dA[3]));
                    __stcs((float4*)(pB + P * 16), make_float4(dB[0], dB[1], dB[2], dB[3]));
                }
            }
        }
        pA0 += KT; pB0 += KT; pA1 += KT; pB1 += KT;
    }
}

// ---------------- launch ----------------
extern "C" void kernel_launch(void* const* d_in, const int* in_sizes, int n_in,
                              void* d_out, int out_size) {
    const float* q   = (const float*)d_in[0];
    const int*   kq  = (const int*)d_in[1];
    const float* ksc = (const float*)d_in[2];
    const float* kz  = (const float*)d_in[3];
    const float* W   = (const float*)d_in[4];
    float* out = (float*)d_out;
    (void)in_sizes; (void)n_in; (void)out_size;

    cudaFuncSetAttribute(k_prep2, cudaFuncAttributeMaxDynamicSharedMemorySize, SMEM_FUSED);
    cudaFuncSetAttribute(k_main,  cudaFuncAttributeMaxDynamicSharedMemorySize, SMEM_MAIN);

    k_G<<<DC, 256>>>(W);
    k_prep2<<<128 + (B_ * LK) / 64, 256, SMEM_FUSED>>>(q, kq, ksc, kz);
    k_main<<<dim3(LK / (KT * KB), LQ / 128, B_), 256, SMEM_MAIN>>>(out);
}

// round 14
// speedup vs baseline: 1.1248x; 1.0027x over previous
#include <cuda_runtime.h>
#include <cuda_bf16.h>
#include <cstdint>
#include <cmath>

#define B_   8
#define LQ   1024
#define LK   8192
#define D_   256
#define DC   128
#define EPSF 1e-6f
#define LN2F 0.69314718055994531f

// ---------------- scratch (no allocations allowed) ----------------
__device__ uint8_t        g_qt8[B_ * LQ * DC];    // q~ = q @ W_up, e4m3 (1 MB)
__device__ float          g_qsq[B_ * LQ];
__device__ uint8_t        g_kc8[B_ * LK * DC];    // dequantized codes, e4m3 (8 MB)
__device__ float          g_ksq[B_ * LK];
__device__ __nv_bfloat16  g_G[DC * DC];           // G = W^T W (bf16)
__device__ __nv_bfloat16  g_Wt[DC * D_];          // W^T (c-major)

// ---------------- fast math ----------------
__device__ __forceinline__ float fast_rcp(float x)  { float r; asm("rcp.approx.f32 %0, %1;"  : "=f"(r) : "f"(x)); return r; }
__device__ __forceinline__ float fast_sqrt(float x) { float r; asm("sqrt.approx.f32 %0, %1;" : "=f"(r) : "f"(x)); return r; }
__device__ __forceinline__ float fast_lg2(float x)  { float r; asm("lg2.approx.f32 %0, %1;"  : "=f"(r) : "f"(x)); return r; }
__device__ __forceinline__ uint16_t pack_e4m3x2(float lo, float hi) {
    uint16_t u;
    asm("cvt.rn.satfinite.e4m3x2.f32 %0, %1, %2;" : "=h"(u) : "f"(hi), "f"(lo));
    return u;
}

// ---------------- mma helpers ----------------
__device__ __forceinline__ uint32_t sptr(const void* p) {
    return (uint32_t)__cvta_generic_to_shared(p);
}
__device__ __forceinline__ void ldsm4(uint32_t& a0, uint32_t& a1, uint32_t& a2, uint32_t& a3, uint32_t addr) {
    asm volatile("ldmatrix.sync.aligned.m8n8.x4.shared.b16 {%0,%1,%2,%3}, [%4];"
                 : "=r"(a0), "=r"(a1), "=r"(a2), "=r"(a3) : "r"(addr));
}
__device__ __forceinline__ void ldsm2(uint32_t& b0, uint32_t& b1, uint32_t addr) {
    asm volatile("ldmatrix.sync.aligned.m8n8.x2.shared.b16 {%0,%1}, [%2];"
                 : "=r"(b0), "=r"(b1) : "r"(addr));
}
__device__ __forceinline__ void mma16816(float& c0, float& c1, float& c2, float& c3,
                                         uint32_t a0, uint32_t a1, uint32_t a2, uint32_t a3,
                                         uint32_t b0, uint32_t b1) {
    asm volatile("mma.sync.aligned.m16n8k16.row.col.f32.bf16.bf16.f32 "
                 "{%0,%1,%2,%3}, {%4,%5,%6,%7}, {%8,%9}, {%0,%1,%2,%3};"
                 : "+f"(c0), "+f"(c1), "+f"(c2), "+f"(c3)
                 : "r"(a0), "r"(a1), "r"(a2), "r"(a3), "r"(b0), "r"(b1));
}
__device__ __forceinline__ void mma16832fp8(float& c0, float& c1, float& c2, float& c3,
                                            uint32_t a0, uint32_t a1, uint32_t a2, uint32_t a3,
                                            uint32_t b0, uint32_t b1) {
    asm volatile("mma.sync.aligned.m16n8k32.row.col.f32.e4m3.e4m3.f32 "
                 "{%0,%1,%2,%3}, {%4,%5,%6,%7}, {%8,%9}, {%0,%1,%2,%3};"
                 : "+f"(c0), "+f"(c1), "+f"(c2), "+f"(c3)
                 : "r"(a0), "r"(a1), "r"(a2), "r"(a3), "r"(b0), "r"(b1));
}
__device__ __forceinline__ void cp16(uint32_t dst, const void* src) {
    asm volatile("cp.async.cg.shared.global [%0], [%1], 16;" :: "r"(dst), "l"(src));
}
__device__ __forceinline__ void cp_commit() { asm volatile("cp.async.commit_group;" ::: "memory"); }
__device__ __forceinline__ void cp_wait0()  { asm volatile("cp.async.wait_group 0;" ::: "memory"); }

// ---------------- kernel 1: G = W^T W + Wt bf16 (512 thr, 4-way d-split, ILP-4) ----------------
__global__ void k_G(const float* __restrict__ W) {
    __shared__ float col[D_];
    __shared__ float red[512];
    const int c1 = blockIdx.x;          // 128 blocks
    const int t  = threadIdx.x;         // 512 threads
    const int c2 = t & 127, h = t >> 7; // h in 0..3

    if (t < D_) {
        float wv = W[t * DC + c1];
        col[t] = wv;
        g_Wt[c1 * D_ + t] = __float2bfloat16(wv);
    }
    __syncthreads();

    float a0 = 0.f, a1 = 0.f, a2 = 0.f, a3 = 0.f;
    const int d0 = h * 64;
    #pragma unroll
    for (int d = 0; d < 64; d += 4) {
        a0 = fmaf(col[d0 + d],     W[(d0 + d) * DC + c2],     a0);
        a1 = fmaf(col[d0 + d + 1], W[(d0 + d + 1) * DC + c2], a1);
        a2 = fmaf(col[d0 + d + 2], W[(d0 + d + 2) * DC + c2], a2);
        a3 = fmaf(col[d0 + d + 3], W[(d0 + d + 3) * DC + c2], a3);
    }
    red[t] = (a0 + a1) + (a2 + a3);
    __syncthreads();
    if (h == 0)
        g_G[c1 * DC + c2] = __float2bfloat16((red[c2] + red[c2 + 128]) +
                                             (red[c2 + 256] + red[c2 + 384]));
}

// ---------------- kernel 2: prepq — q~ = q @ W via MMA + q_sq ----------------
#define QR 64
#define QSTRIDE 264
#define SMEM_PREPQ (QR * QSTRIDE * 2 + 128 * QSTRIDE * 2 + 128 * 4 + QR * 4 + 256)

__global__ void k_prepq(const float* __restrict__ q) {
    extern __shared__ char sm[];
    __nv_bfloat16* qs  = (__nv_bfloat16*)sm;                 // [64][264]
    __nv_bfloat16* Wts = qs + QR * QSTRIDE;                  // [128][264]
    float*         par = (float*)(Wts + 128 * QSTRIDE);      // [128]
    float*         qsq = par + 128;                          // [64]

    const int t  = threadIdx.x;          // 256
    const int r0 = blockIdx.x * QR;      // 128 blocks

    {
        const float4* src = (const float4*)(q + (size_t)r0 * D_);
        #pragma unroll
        for (int i = 0; i < 16; i++) {
            int idx = t + i * 256;
            int row = idx >> 6, c4 = (idx & 63) * 4;
            float4 v = src[idx];
            *(__nv_bfloat162*)&qs[row * QSTRIDE + c4]     = __floats2bfloat162_rn(v.x, v.y);
            *(__nv_bfloat162*)&qs[row * QSTRIDE + c4 + 2] = __floats2bfloat162_rn(v.z, v.w);
        }
    }
    if (t < 128) {
        const float4* rowp = (const float4*)(q + (size_t)(r0 + (t >> 1)) * D_) + (t & 1) * 32;
        float ss = 0.f;
        #pragma unroll 8
        for (int i = 0; i < 32; i++) {
            float4 v = rowp[i];
            ss += v.x * v.x + v.y * v.y + v.z * v.z + v.w * v.w;
        }
        par[t] = ss;
    }
    {
        #pragma unroll
        for (int i = 0; i < 16; i++) {
            int idx = t + i * 256;
            int r = idx >> 5, c8 = (idx & 31) * 8;
            *(uint4*)&Wts[r * QSTRIDE + c8] = ((const uint4*)g_Wt)[idx];
        }
    }
    __syncthreads();
    if (t < QR) qsq[t] = par[2 * t] + par[2 * t + 1];

    const int w = t >> 5, lane = t & 31;
    const int m0 = (w >> 2) * 32, n0 = (w & 3) * 32;
    const int gid = lane >> 2, tid2 = lane & 3;
    const int arow = lane & 15, acol = ((lane >> 4) << 3);
    const int brow = lane & 7,  bcol = (((lane >> 3) & 1) << 3);

    float acc[2][4][4];
    #pragma unroll
    for (int i = 0; i < 2; i++)
        #pragma unroll
        for (int j = 0; j < 4; j++)
            #pragma unroll
            for (int c = 0; c < 4; c++) acc[i][j][c] = 0.f;

    #pragma unroll
    for (int ks = 0; ks < 16; ks++) {
        const int k0 = ks * 16;
        uint32_t A[2][4], Bf[4][2];
        #pragma unroll
        for (int ms = 0; ms < 2; ms++)
            ldsm4(A[ms][0], A[ms][1], A[ms][2], A[ms][3],
                  sptr(&qs[(m0 + ms * 16 + arow) * QSTRIDE + k0 + acol]));
        #pragma unroll
        for (int ns = 0; ns < 4; ns++)
            ldsm2(Bf[ns][0], Bf[ns][1],
                  sptr(&Wts[(n0 + ns * 8 + brow) * QSTRIDE + k0 + bcol]));
        #pragma unroll
        for (int ms = 0; ms < 2; ms++)
            #pragma unroll
            for (int ns = 0; ns < 4; ns++)
                mma16816(acc[ms][ns][0], acc[ms][ns][1], acc[ms][ns][2], acc[ms][ns][3],
                         A[ms][0], A[ms][1], A[ms][2], A[ms][3], Bf[ns][0], Bf[ns][1]);
    }

    #pragma unroll
    for (int ms = 0; ms < 2; ms++) {
        const int rA = m0 + ms * 16 + gid, rB = rA + 8;
        #pragma unroll
        for (int ns = 0; ns < 4; ns++) {
            const int c0 = n0 + ns * 8 + tid2 * 2;
            *(uint16_t*)&g_qt8[(size_t)(r0 + rA) * DC + c0] = pack_e4m3x2(acc[ms][ns][0], acc[ms][ns][1]);
            *(uint16_t*)&g_qt8[(size_t)(r0 + rB) * DC + c0] = pack_e4m3x2(acc[ms][ns][2], acc[ms][ns][3]);
        }
    }
    __syncthreads();
    if (t < QR) g_qsq[r0 + t] = qsq[t];
}

// ---------------- kernel 3: prepk — dequant + k_sq (64 rows/block, 52.7KB -> 4 CTA/SM) ----------------
#define PSTRIDE 136
#define SMEM_PREPK (64 * PSTRIDE * 2 + 128 * PSTRIDE * 2 + 64 * 4 + 256)

__global__ void __launch_bounds__(256, 4) k_prepk(const int* __restrict__ kq,
                                                  const float* __restrict__ kscale,
                                                  const float* __restrict__ kzero) {
    extern __shared__ char sm[];
    __nv_bfloat16* kcs  = (__nv_bfloat16*)sm;                 // [64][136]
    __nv_bfloat16* Gs   = kcs + 64 * PSTRIDE;                 // [128][136]
    float*         ksqs = (float*)(Gs + 128 * PSTRIDE);       // [64]

    const int t    = threadIdx.x;        // 256
    const int row0 = blockIdx.x * 64;    // 1024 blocks
    const int b    = row0 / LK;

    {
        const int c4 = (t & 31) * 4;
        const float4 sc = *(const float4*)(kscale + b * DC + c4);
        const float4 zr = *(const float4*)(kzero + b * DC + c4);
        const int rb = t >> 5;
        #pragma unroll
        for (int i = 0; i < 8; i++) {
            const int r = rb + i * 8;
            const int4 code = *(const int4*)(kq + (size_t)(row0 + r) * DC + c4);
            float v0 = sc.x * ((float)code.x - zr.x);
            float v1 = sc.y * ((float)code.y - zr.y);
            float v2 = sc.z * ((float)code.z - zr.z);
            float v3 = sc.w * ((float)code.w - zr.w);
            __nv_bfloat162 p0, p1;
            p0.x = __float2bfloat16(v0); p0.y = __float2bfloat16(v1);
            p1.x = __float2bfloat16(v2); p1.y = __float2bfloat16(v3);
            *(__nv_bfloat162*)&kcs[r * PSTRIDE + c4]     = p0;
            *(__nv_bfloat162*)&kcs[r * PSTRIDE + c4 + 2] = p1;
            uint32_t pk = (uint32_t)pack_e4m3x2(v0, v1) | ((uint32_t)pack_e4m3x2(v2, v3) << 16);
            *(uint32_t*)&g_kc8[(size_t)(row0 + r) * DC + c4] = pk;
        }
    }
    {
        const int r = t >> 1, ch = (t & 1) * 64;
        const uint4* src = (const uint4*)(g_G + r * DC + ch);
        #pragma unroll
        for (int i = 0; i < 8; i++) *(uint4*)&Gs[r * PSTRIDE + ch + i * 8] = src[i];
    }
    if (t < 64) ksqs[t] = 0.f;
    __syncthreads();

    const int w = t >> 5, lane = t & 31;
    const int m0 = (w >> 2) * 32, n0 = (w & 3) * 32;
    const int gid = lane >> 2, tid2 = lane & 3;
    const int arow = lane & 15, acol = ((lane >> 4) << 3);
    const int brow = lane & 7,  bcol = (((lane >> 3) & 1) << 3);

    float acc[2][4][4];
    #pragma unroll
    for (int i = 0; i < 2; i++)
        #pragma unroll
        for (int j = 0; j < 4; j++)
            #pragma unroll
            for (int c = 0; c < 4; c++) acc[i][j][c] = 0.f;

    #pragma unroll
    for (int ks = 0; ks < 8; ks++) {
        const int k0 = ks * 16;
        uint32_t A[2][4], Bf[4][2];
        #pragma unroll
        for (int ms = 0; ms < 2; ms++)
            ldsm4(A[ms][0], A[ms][1], A[ms][2], A[ms][3],
                  sptr(&kcs[(m0 + ms * 16 + arow) * PSTRIDE + k0 + acol]));
        #pragma unroll
        for (int ns = 0; ns < 4; ns++)
            ldsm2(Bf[ns][0], Bf[ns][1],
                  sptr(&Gs[(n0 + ns * 8 + brow) * PSTRIDE + k0 + bcol]));
        #pragma unroll
        for (int ms = 0; ms < 2; ms++)
            #pragma unroll
            for (int ns = 0; ns < 4; ns++)
                mma16816(acc[ms][ns][0], acc[ms][ns][1], acc[ms][ns][2], acc[ms][ns][3],
                         A[ms][0], A[ms][1], A[ms][2], A[ms][3], Bf[ns][0], Bf[ns][1]);
    }

    #pragma unroll
    for (int ms = 0; ms < 2; ms++) {
        const int rA = m0 + ms * 16 + gid, rB = rA + 8;
        float sA = 0.f, sB = 0.f;
        #pragma unroll
        for (int ns = 0; ns < 4; ns++) {
            const int c0 = n0 + ns * 8 + tid2 * 2;
            sA += acc[ms][ns][0] * __bfloat162float(kcs[rA * PSTRIDE + c0]);
            sA += acc[ms][ns][1] * __bfloat162float(kcs[rA * PSTRIDE + c0 + 1]);
            sB += acc[ms][ns][2] * __bfloat162float(kcs[rB * PSTRIDE + c0]);
            sB += acc[ms][ns][3] * __bfloat162float(kcs[rB * PSTRIDE + c0 + 1]);
        }
        atomicAdd(&ksqs[rA], sA);
        atomicAdd(&ksqs[rB], sB);
    }
    __syncthreads();
    if (t < 64) g_ksq[row0 + t] = ksqs[t];
}

// ---------------- kernel 4: main — FP8 MMA, 128x64 tile (unchanged, 90.6 us) ----------------
#define KB 4
#define KT 64
#define PS8 144
#define QT8_BYTES (128 * PS8)
#define KT8_BYTES (KT * PS8)
#define SM_KT8    QT8_BYTES
#define SM_NRM    (QT8_BYTES + 2 * KT8_BYTES)
#define SMEM_MAIN (SM_NRM + 2 * 128 * 4 + 2 * KT * 4 + 256)

__global__ void __launch_bounds__(256, 3) k_main(float* __restrict__ out) {
    extern __shared__ char sm[];
    uint8_t* qts  = (uint8_t*)sm;
    uint8_t* kcs  = (uint8_t*)sm + SM_KT8;
    float*   qsqs = (float*)(sm + SM_NRM);
    float*   rqs  = qsqs + 128;
    float*   ksqr = rqs + 128;

    const int t = threadIdx.x;
    const int kbb = blockIdx.x, qb = blockIdx.y, b = blockIdx.z;
    const int q0 = qb * 128, kbase = kbb * (KT * KB);

    {
        const int rq = t >> 1, chb = (t & 1) * 64;
        const uint4* s1 = (const uint4*)(g_qt8 + ((size_t)(b * LQ + q0 + rq)) * DC + chb);
        #pragma unroll
        for (int i = 0; i < 4; i++) *(uint4*)(qts + rq * PS8 + chb + i * 16) = s1[i];
    }
    if (t < 128) {
        float qs = g_qsq[b * LQ + q0 + t];
        qsqs[t] = qs;
        rqs[t] = 1.f - fminf(qs, 1.f - EPSF);
    }

    const int rk = t >> 2, kchb = (t & 3) * 32;
    const int lk_ = rk & 15;
    const int prk = (rk & ~15) | (((lk_ >> 1) & 1) * 8 + ((lk_ >> 2) << 1) + (lk_ & 1));

    {
        const uint32_t dst = sptr(kcs + prk * PS8 + kchb);
        const char* src = (const char*)(g_kc8 + ((size_t)(b * LK + kbase + rk)) * DC + kchb);
        cp16(dst, src);
        cp16(dst + 16, src + 16);
        if (t < 16) cp16(sptr(&ksqr[t * 4]), g_ksq + b * LK + kbase + t * 4);
    }
    cp_commit();

    const int w = t >> 5, lane = t & 31;
    const int m0 = (w & 3) * 32, nw0 = (w >> 2) * 32;
    const int gid = lane >> 2, tid2 = lane & 3;
    const int arow = lane & 15, acolb = ((lane >> 4) << 4);
    const int brow16 = (lane & 7) + ((lane >> 4) << 3);
    const int bcolb = (((lane >> 3) & 1) << 4);

    const float N0C = EPSF + EPSF * EPSF;
    const float H0  = 0.5f * N0C;
    const float C0  = LN2F * (2.f - fast_lg2(N0C));
    const float TH  = 50.5f * N0C;
    const float I2N = 2.f * fast_rcp(N0C);

    __syncthreads();

    const int rowA0 = m0 + gid, rowA1 = m0 + 16 + gid;
    float aA[2], aB[2];
    aA[0] = qsqs[rowA0] + H0;      aB[0] = qsqs[rowA0 + 8] + H0;
    aA[1] = qsqs[rowA1] + H0;      aB[1] = qsqs[rowA1 + 8] + H0;
    bool uniQ = (aA[0] >= 1.f) & (aB[0] >= 1.f) & (aA[1] >= 1.f) & (aB[1] >= 1.f);
    float* pA0 = out + ((size_t)(b * LQ + q0 + rowA0)) * LK + kbase + nw0 + 4 * tid2;
    float* pB0 = pA0 + (size_t)8 * LK;
    float* pA1 = out + ((size_t)(b * LQ + q0 + rowA1)) * LK + kbase + nw0 + 4 * tid2;
    float* pB1 = pA1 + (size_t)8 * LK;

    for (int kb = 0; kb < KB; kb++) {
        cp_wait0();
        __syncthreads();

        const float* kraw = ksqr + (kb & 1) * KT;
        float4 ks4[2];
        ks4[0] = *(const float4*)&kraw[nw0 + 4 * tid2];
        ks4[1] = *(const float4*)&kraw[nw0 + 16 + 4 * tid2];

        if (kb + 1 < KB) {
            const int nb = (kb + 1) & 1;
            const uint32_t dst = sptr(kcs + nb * KT8_BYTES + prk * PS8 + kchb);
            const char* src = (const char*)(g_kc8 + ((size_t)(b * LK + kbase + (kb + 1) * KT + rk)) * DC + kchb);
            cp16(dst, src);
            cp16(dst + 16, src + 16);
            if (t < 16) cp16(sptr(&ksqr[nb * KT + t * 4]),
                             g_ksq + b * LK + kbase + (kb + 1) * KT + t * 4);
            cp_commit();
        }

        const uint8_t* kbuf = kcs + (kb & 1) * KT8_BYTES;

        float acc[2][4][4];
        #pragma unroll
        for (int i = 0; i < 2; i++)
            #pragma unroll
            for (int j = 0; j < 4; j++)
                #pragma unroll
                for (int c = 0; c < 4; c++) acc[i][j][c] = 0.f;

        #pragma unroll
        for (int ks = 0; ks < 4; ks++) {
            const int k0b = ks * 32;
            uint32_t A[2][4], Bf[2][4];
            #pragma unroll
            for (int ms = 0; ms < 2; ms++)
                ldsm4(A[ms][0], A[ms][1], A[ms][2], A[ms][3],
                      sptr(qts + (m0 + ms * 16 + arow) * PS8 + k0b + acolb));
            #pragma unroll
            for (int P = 0; P < 2; P++)
                ldsm4(Bf[P][0], Bf[P][1], Bf[P][2], Bf[P][3],
                      sptr(kbuf + (nw0 + P * 16 + brow16) * PS8 + k0b + bcolb));
            #pragma unroll
            for (int ms = 0; ms < 2; ms++)
                #pragma unroll
                for (int P = 0; P < 2; P++) {
                    mma16832fp8(acc[ms][2*P][0], acc[ms][2*P][1], acc[ms][2*P][2], acc[ms][2*P][3],
                                A[ms][0], A[ms][1], A[ms][2], A[ms][3], Bf[P][0], Bf[P][1]);
                    mma16832fp8(acc[ms][2*P+1][0], acc[ms][2*P+1][1], acc[ms][2*P+1][2], acc[ms][2*P+1][3],
                                A[ms][0], A[ms][1], A[ms][2], A[ms][3], Bf[P][2], Bf[P][3]);
                }
        }

        bool uni = uniQ &&
                   ks4[0].x >= 1.f - EPSF && ks4[0].y >= 1.f - EPSF &&
                   ks4[0].z >= 1.f - EPSF && ks4[0].w >= 1.f - EPSF &&
                   ks4[1].x >= 1.f - EPSF && ks4[1].y >= 1.f - EPSF &&
                   ks4[1].z >= 1.f - EPSF && ks4[1].w >= 1.f - EPSF;

        if (uni) {
            #pragma unroll
            for (int ms = 0; ms < 2; ms++) {
                float* pA = ms ? pA1 : pA0;
                float* pB = ms ? pB1 : pB0;
                #pragma unroll
                for (int P = 0; P < 2; P++) {
                    const float4 kk = ks4[P];
                    const float ksv[4] = { kk.x, kk.y, kk.z, kk.w };
                    float vA[4] = { acc[ms][2*P][0], acc[ms][2*P][1], acc[ms][2*P+1][0], acc[ms][2*P+1][1] };
                    float vB[4] = { acc[ms][2*P][2], acc[ms][2*P][3], acc[ms][2*P+1][2], acc[ms][2*P+1][3] };

                    float xA[4], xB[4], dA[4], dB[4];
                    bool bad = false;
                    #pragma unroll
                    for (int j = 0; j < 4; j++) {
                        xA[j] = fmaxf(fmaf(-2.f, vA[j], aA[ms] + ksv[j]), H0);
                        xB[j] = fmaxf(fmaf(-2.f, vB[j], aB[ms] + ksv[j]), H0);
                        bad |= (xA[j] < TH) | (xB[j] < TH);
                        dA[j] = fmaf(fast_lg2(xA[j]), LN2F, C0);
                        dB[j] = fmaf(fast_lg2(xB[j]), LN2F, C0);
                    }
                    if (bad) {
                        #pragma unroll
                        for (int j = 0; j < 4; j++) {
                            float tA = (xA[j] - H0) * I2N;
                            float sA = fast_sqrt(fmaf(tA, tA, 2.f * tA));
                            dA[j] = LN2F * fast_lg2(1.f + tA + sA);
                            float tB = (xB[j] - H0) * I2N;
                            float sB = fast_sqrt(fmaf(tB, tB, 2.f * tB));
                            dB[j] = LN2F * fast_lg2(1.f + tB + sB);
                        }
                    }
                    __stcs((float4*)(pA + P * 16), make_float4(dA[0], dA[1], dA[2], dA[3]));
                    __stcs((float4*)(pB + P * 16), make_float4(dB[0], dB[1], dB[2], dB[3]));
                }
            }
        } else {
            #pragma unroll
            for (int ms = 0; ms < 2; ms++) {
                const int rA = m0 + ms * 16 + gid, rB = rA + 8;
                const float qsA = qsqs[rA], qsB = qsqs[rB];
                const float rqA = rqs[rA],  rqB = rqs[rB];
                float* pA = ms ? pA1 : pA0;
                float* pB = ms ? pB1 : pB0;
                #pragma unroll
                for (int P = 0; P < 2; P++) {
                    const float4 kk = ks4[P];
                    const float ksv[4] = { kk.x, kk.y, kk.z, kk.w };
                    float vA[4] = { acc[ms][2*P][0], acc[ms][2*P][1], acc[ms][2*P+1][0], acc[ms][2*P+1][1] };
                    float vB[4] = { acc[ms][2*P][2], acc[ms][2*P][3], acc[ms][2*P+1][2], acc[ms][2*P+1][3] };

                    float dA[4], dB[4];
                    #pragma unroll
                    for (int j = 0; j < 4; j++) {
                        const float rkj = 1.f - fminf(ksv[j], 1.f - EPSF);
                        float uA = 2.f * fmaxf(fmaf(-2.f, vA[j], qsA + ksv[j]), 0.f);
                        float nA = fmaf(rqA, rkj, EPSF);
                        float uB = 2.f * fmaxf(fmaf(-2.f, vB[j], qsB + ksv[j]), 0.f);
                        float nB = fmaf(rqB, rkj, EPSF);
                        if (uA >= 100.f * nA) {
                            dA[j] = LN2F * (1.f + fast_lg2(uA + nA) - fast_lg2(nA));
                        } else {
                            float tA = uA * fast_rcp(nA);
                            float sA = fast_sqrt(fmaf(tA, tA, 2.f * tA));
                            dA[j] = LN2F * fast_lg2(1.f + tA + sA);
                        }
                        if (uB >= 100.f * nB) {
                            dB[j] = LN2F * (1.f + fast_lg2(uB + nB) - fast_lg2(nB));
                        } else {
                            float tB = uB * fast_rcp(nB);
                            float sB = fast_sqrt(fmaf(tB, tB, 2.f * tB));
                            dB[j] = LN2F * fast_lg2(1.f + tB + sB);
                        }
                    }
                    __stcs((float4*)(pA + P * 16), make_float4(dA[0], dA[1], dA[2], dA[3]));
                    __stcs((float4*)(pB + P * 16), make_float4(dB[0], dB[1], dB[2], dB[3]));
                }
            }
        }
        pA0 += KT; pB0 += KT; pA1 += KT; pB1 += KT;
    }
}

// ---------------- launch ----------------
extern "C" void kernel_launch(void* const* d_in, const int* in_sizes, int n_in,
                              void* d_out, int out_size) {
    const float* q   = (const float*)d_in[0];
    const int*   kq  = (const int*)d_in[1];
    const float* ksc = (const float*)d_in[2];
    const float* kz  = (const float*)d_in[3];
    const float* W   = (const float*)d_in[4];
    float* out = (float*)d_out;
    (void)in_sizes; (void)n_in; (void)out_size;

    cudaFuncSetAttribute(k_prepq, cudaFuncAttributeMaxDynamicSharedMemorySize, SMEM_PREPQ);
    cudaFuncSetAttribute(k_prepk, cudaFuncAttributeMaxDynamicSharedMemorySize, SMEM_PREPK);
    cudaFuncSetAttribute(k_main,  cudaFuncAttributeMaxDynamicSharedMemorySize, SMEM_MAIN);

    k_G<<<DC, 512>>>(W);
    k_prepq<<<(B_ * LQ) / QR, 256, SMEM_PREPQ>>>(q);
    k_prepk<<<(B_ * LK) / 64, 256, SMEM_PREPK>>>(kq, ksc, kz);
    k_main<<<dim3(LK / (KT * KB), LQ / 128, B_), 256, SMEM_MAIN>>>(out);
}

// round 15
// speedup vs baseline: 1.1777x; 1.0471x over previous
#include <cuda_runtime.h>
#include <cuda_bf16.h>
#include <cstdint>
#include <cmath>

#define B_   8
#define LQ   1024
#define LK   8192
#define D_   256
#define DC   128
#define EPSF 1e-6f
#define LN2F 0.69314718055994531f

// ---------------- scratch (no allocations allowed) ----------------
__device__ uint8_t        g_qt8[B_ * LQ * DC];    // q~ = q @ W_up, e4m3 (1 MB)
__device__ float          g_qsq[B_ * LQ];
__device__ uint8_t        g_kc8[B_ * LK * DC];    // dequantized codes, e4m3 (8 MB)
__device__ float          g_ksq[B_ * LK];
__device__ __nv_bfloat16  g_G[DC * DC];           // G = W^T W (bf16)
__device__ __nv_bfloat16  g_Wt[DC * D_];          // W^T (c-major)

// ---------------- fast math ----------------
__device__ __forceinline__ float fast_rcp(float x)  { float r; asm("rcp.approx.f32 %0, %1;"  : "=f"(r) : "f"(x)); return r; }
__device__ __forceinline__ float fast_sqrt(float x) { float r; asm("sqrt.approx.f32 %0, %1;" : "=f"(r) : "f"(x)); return r; }
__device__ __forceinline__ float fast_lg2(float x)  { float r; asm("lg2.approx.f32 %0, %1;"  : "=f"(r) : "f"(x)); return r; }
__device__ __forceinline__ uint16_t pack_e4m3x2(float lo, float hi) {
    uint16_t u;
    asm("cvt.rn.satfinite.e4m3x2.f32 %0, %1, %2;" : "=h"(u) : "f"(hi), "f"(lo));
    return u;
}

// ---------------- mma helpers ----------------
__device__ __forceinline__ uint32_t sptr(const void* p) {
    return (uint32_t)__cvta_generic_to_shared(p);
}
__device__ __forceinline__ void ldsm4(uint32_t& a0, uint32_t& a1, uint32_t& a2, uint32_t& a3, uint32_t addr) {
    asm volatile("ldmatrix.sync.aligned.m8n8.x4.shared.b16 {%0,%1,%2,%3}, [%4];"
                 : "=r"(a0), "=r"(a1), "=r"(a2), "=r"(a3) : "r"(addr));
}
__device__ __forceinline__ void ldsm2(uint32_t& b0, uint32_t& b1, uint32_t addr) {
    asm volatile("ldmatrix.sync.aligned.m8n8.x2.shared.b16 {%0,%1}, [%2];"
                 : "=r"(b0), "=r"(b1) : "r"(addr));
}
__device__ __forceinline__ void mma16816(float& c0, float& c1, float& c2, float& c3,
                                         uint32_t a0, uint32_t a1, uint32_t a2, uint32_t a3,
                                         uint32_t b0, uint32_t b1) {
    asm volatile("mma.sync.aligned.m16n8k16.row.col.f32.bf16.bf16.f32 "
                 "{%0,%1,%2,%3}, {%4,%5,%6,%7}, {%8,%9}, {%0,%1,%2,%3};"
                 : "+f"(c0), "+f"(c1), "+f"(c2), "+f"(c3)
                 : "r"(a0), "r"(a1), "r"(a2), "r"(a3), "r"(b0), "r"(b1));
}
__device__ __forceinline__ void mma16832fp8(float& c0, float& c1, float& c2, float& c3,
                                            uint32_t a0, uint32_t a1, uint32_t a2, uint32_t a3,
                                            uint32_t b0, uint32_t b1) {
    asm volatile("mma.sync.aligned.m16n8k32.row.col.f32.e4m3.e4m3.f32 "
                 "{%0,%1,%2,%3}, {%4,%5,%6,%7}, {%8,%9}, {%0,%1,%2,%3};"
                 : "+f"(c0), "+f"(c1), "+f"(c2), "+f"(c3)
                 : "r"(a0), "r"(a1), "r"(a2), "r"(a3), "r"(b0), "r"(b1));
}
__device__ __forceinline__ void cp16(uint32_t dst, const void* src) {
    asm volatile("cp.async.cg.shared.global [%0], [%1], 16;" :: "r"(dst), "l"(src));
}
__device__ __forceinline__ void cp_commit() { asm volatile("cp.async.commit_group;" ::: "memory"); }
__device__ __forceinline__ void cp_wait0()  { asm volatile("cp.async.wait_group 0;" ::: "memory"); }

// ---------------- kernel 1: G = W^T W + Wt bf16 (512 thr, 4-way d-split, ILP-4) ----------------
__global__ void k_G(const float* __restrict__ W) {
    __shared__ float col[D_];
    __shared__ float red[512];
    const int c1 = blockIdx.x;          // 128 blocks
    const int t  = threadIdx.x;         // 512 threads
    const int c2 = t & 127, h = t >> 7; // h in 0..3

    if (t < D_) {
        float wv = W[t * DC + c1];
        col[t] = wv;
        g_Wt[c1 * D_ + t] = __float2bfloat16(wv);
    }
    __syncthreads();

    float a0 = 0.f, a1 = 0.f, a2 = 0.f, a3 = 0.f;
    const int d0 = h * 64;
    #pragma unroll
    for (int d = 0; d < 64; d += 4) {
        a0 = fmaf(col[d0 + d],     W[(d0 + d) * DC + c2],     a0);
        a1 = fmaf(col[d0 + d + 1], W[(d0 + d + 1) * DC + c2], a1);
        a2 = fmaf(col[d0 + d + 2], W[(d0 + d + 2) * DC + c2], a2);
        a3 = fmaf(col[d0 + d + 3], W[(d0 + d + 3) * DC + c2], a3);
    }
    red[t] = (a0 + a1) + (a2 + a3);
    __syncthreads();
    if (h == 0)
        g_G[c1 * DC + c2] = __float2bfloat16((red[c2] + red[c2 + 128]) +
                                             (red[c2 + 256] + red[c2 + 384]));
}

// ---------------- kernel 2: prepq — q~ = q @ W via MMA + q_sq ----------------
#define QR 64
#define QSTRIDE 264
#define SMEM_PREPQ (QR * QSTRIDE * 2 + 128 * QSTRIDE * 2 + 128 * 4 + QR * 4 + 256)

__global__ void k_prepq(const float* __restrict__ q) {
    extern __shared__ char sm[];
    __nv_bfloat16* qs  = (__nv_bfloat16*)sm;                 // [64][264]
    __nv_bfloat16* Wts = qs + QR * QSTRIDE;                  // [128][264]
    float*         par = (float*)(Wts + 128 * QSTRIDE);      // [128]
    float*         qsq = par + 128;                          // [64]

    const int t  = threadIdx.x;          // 256
    const int r0 = blockIdx.x * QR;      // 128 blocks

    {
        const float4* src = (const float4*)(q + (size_t)r0 * D_);
        #pragma unroll
        for (int i = 0; i < 16; i++) {
            int idx = t + i * 256;
            int row = idx >> 6, c4 = (idx & 63) * 4;
            float4 v = src[idx];
            *(__nv_bfloat162*)&qs[row * QSTRIDE + c4]     = __floats2bfloat162_rn(v.x, v.y);
            *(__nv_bfloat162*)&qs[row * QSTRIDE + c4 + 2] = __floats2bfloat162_rn(v.z, v.w);
        }
    }
    if (t < 128) {
        const float4* rowp = (const float4*)(q + (size_t)(r0 + (t >> 1)) * D_) + (t & 1) * 32;
        float ss = 0.f;
        #pragma unroll 8
        for (int i = 0; i < 32; i++) {
            float4 v = rowp[i];
            ss += v.x * v.x + v.y * v.y + v.z * v.z + v.w * v.w;
        }
        par[t] = ss;
    }
    {
        #pragma unroll
        for (int i = 0; i < 16; i++) {
            int idx = t + i * 256;
            int r = idx >> 5, c8 = (idx & 31) * 8;
            *(uint4*)&Wts[r * QSTRIDE + c8] = ((const uint4*)g_Wt)[idx];
        }
    }
    __syncthreads();
    if (t < QR) qsq[t] = par[2 * t] + par[2 * t + 1];

    const int w = t >> 5, lane = t & 31;
    const int m0 = (w >> 2) * 32, n0 = (w & 3) * 32;
    const int gid = lane >> 2, tid2 = lane & 3;
    const int arow = lane & 15, acol = ((lane >> 4) << 3);
    const int brow = lane & 7,  bcol = (((lane >> 3) & 1) << 3);

    float acc[2][4][4];
    #pragma unroll
    for (int i = 0; i < 2; i++)
        #pragma unroll
        for (int j = 0; j < 4; j++)
            #pragma unroll
            for (int c = 0; c < 4; c++) acc[i][j][c] = 0.f;

    #pragma unroll
    for (int ks = 0; ks < 16; ks++) {
        const int k0 = ks * 16;
        uint32_t A[2][4], Bf[4][2];
        #pragma unroll
        for (int ms = 0; ms < 2; ms++)
            ldsm4(A[ms][0], A[ms][1], A[ms][2], A[ms][3],
                  sptr(&qs[(m0 + ms * 16 + arow) * QSTRIDE + k0 + acol]));
        #pragma unroll
        for (int ns = 0; ns < 4; ns++)
            ldsm2(Bf[ns][0], Bf[ns][1],
                  sptr(&Wts[(n0 + ns * 8 + brow) * QSTRIDE + k0 + bcol]));
        #pragma unroll
        for (int ms = 0; ms < 2; ms++)
            #pragma unroll
            for (int ns = 0; ns < 4; ns++)
                mma16816(acc[ms][ns][0], acc[ms][ns][1], acc[ms][ns][2], acc[ms][ns][3],
                         A[ms][0], A[ms][1], A[ms][2], A[ms][3], Bf[ns][0], Bf[ns][1]);
    }

    #pragma unroll
    for (int ms = 0; ms < 2; ms++) {
        const int rA = m0 + ms * 16 + gid, rB = rA + 8;
        #pragma unroll
        for (int ns = 0; ns < 4; ns++) {
            const int c0 = n0 + ns * 8 + tid2 * 2;
            *(uint16_t*)&g_qt8[(size_t)(r0 + rA) * DC + c0] = pack_e4m3x2(acc[ms][ns][0], acc[ms][ns][1]);
            *(uint16_t*)&g_qt8[(size_t)(r0 + rB) * DC + c0] = pack_e4m3x2(acc[ms][ns][2], acc[ms][ns][3]);
        }
    }
    __syncthreads();
    if (t < QR) g_qsq[r0 + t] = qsq[t];
}

// ---------------- kernel 3: prepk — dequant + k_sq (128 rows/block, r10-proven config) ----------------
#define PSTRIDE 136
#define SMEM_PREPK (2 * 128 * PSTRIDE * 2 + 512)

__global__ void k_prepk(const int* __restrict__ kq,
                        const float* __restrict__ kscale,
                        const float* __restrict__ kzero) {
    extern __shared__ char sm[];
    __nv_bfloat16* kcs  = (__nv_bfloat16*)sm;                 // [128][136]
    __nv_bfloat16* Gs   = kcs + 128 * PSTRIDE;                // [128][136]
    float*         ksqs = (float*)(Gs + 128 * PSTRIDE);       // [128]

    const int t    = threadIdx.x;        // 256
    const int row0 = blockIdx.x * 128;   // 512 blocks
    const int b    = row0 / LK;

    {
        const int c4 = (t & 31) * 4;
        const float4 sc = *(const float4*)(kscale + b * DC + c4);
        const float4 zr = *(const float4*)(kzero + b * DC + c4);
        const int rb = t >> 5;
        #pragma unroll
        for (int i = 0; i < 16; i++) {
            const int r = rb + i * 8;
            const int4 code = *(const int4*)(kq + (size_t)(row0 + r) * DC + c4);
            float v0 = sc.x * ((float)code.x - zr.x);
            float v1 = sc.y * ((float)code.y - zr.y);
            float v2 = sc.z * ((float)code.z - zr.z);
            float v3 = sc.w * ((float)code.w - zr.w);
            __nv_bfloat162 p0, p1;
            p0.x = __float2bfloat16(v0); p0.y = __float2bfloat16(v1);
            p1.x = __float2bfloat16(v2); p1.y = __float2bfloat16(v3);
            *(__nv_bfloat162*)&kcs[r * PSTRIDE + c4]     = p0;
            *(__nv_bfloat162*)&kcs[r * PSTRIDE + c4 + 2] = p1;
            uint32_t pk = (uint32_t)pack_e4m3x2(v0, v1) | ((uint32_t)pack_e4m3x2(v2, v3) << 16);
            *(uint32_t*)&g_kc8[(size_t)(row0 + r) * DC + c4] = pk;
        }
    }
    {
        const int r = t >> 1, ch = (t & 1) * 64;
        const uint4* src = (const uint4*)(g_G + r * DC + ch);
        #pragma unroll
        for (int i = 0; i < 8; i++) *(uint4*)&Gs[r * PSTRIDE + ch + i * 8] = src[i];
    }
    if (t < 128) ksqs[t] = 0.f;
    __syncthreads();

    const int w = t >> 5, lane = t & 31;
    const int m0 = (w >> 2) * 64, n0 = (w & 3) * 32;
    const int gid = lane >> 2, tid2 = lane & 3;
    const int arow = lane & 15, acol = ((lane >> 4) << 3);
    const int brow = lane & 7,  bcol = (((lane >> 3) & 1) << 3);

    float acc[4][4][4];
    #pragma unroll
    for (int i = 0; i < 4; i++)
        #pragma unroll
        for (int j = 0; j < 4; j++)
            #pragma unroll
            for (int c = 0; c < 4; c++) acc[i][j][c] = 0.f;

    #pragma unroll
    for (int ks = 0; ks < 8; ks++) {
        const int k0 = ks * 16;
        uint32_t A[4][4], Bf[4][2];
        #pragma unroll
        for (int ms = 0; ms < 4; ms++)
            ldsm4(A[ms][0], A[ms][1], A[ms][2], A[ms][3],
                  sptr(&kcs[(m0 + ms * 16 + arow) * PSTRIDE + k0 + acol]));
        #pragma unroll
        for (int ns = 0; ns < 4; ns++)
            ldsm2(Bf[ns][0], Bf[ns][1],
                  sptr(&Gs[(n0 + ns * 8 + brow) * PSTRIDE + k0 + bcol]));
        #pragma unroll
        for (int ms = 0; ms < 4; ms++)
            #pragma unroll
            for (int ns = 0; ns < 4; ns++)
                mma16816(acc[ms][ns][0], acc[ms][ns][1], acc[ms][ns][2], acc[ms][ns][3],
                         A[ms][0], A[ms][1], A[ms][2], A[ms][3], Bf[ns][0], Bf[ns][1]);
    }

    #pragma unroll
    for (int ms = 0; ms < 4; ms++) {
        const int rA = m0 + ms * 16 + gid, rB = rA + 8;
        float sA = 0.f, sB = 0.f;
        #pragma unroll
        for (int ns = 0; ns < 4; ns++) {
            const int c0 = n0 + ns * 8 + tid2 * 2;
            sA += acc[ms][ns][0] * __bfloat162float(kcs[rA * PSTRIDE + c0]);
            sA += acc[ms][ns][1] * __bfloat162float(kcs[rA * PSTRIDE + c0 + 1]);
            sB += acc[ms][ns][2] * __bfloat162float(kcs[rB * PSTRIDE + c0]);
            sB += acc[ms][ns][3] * __bfloat162float(kcs[rB * PSTRIDE + c0 + 1]);
        }
        atomicAdd(&ksqs[rA], sA);
        atomicAdd(&ksqs[rB], sB);
    }
    __syncthreads();
    if (t < 128) g_ksq[row0 + t] = ksqs[t];
}

// ---------------- kernel 4: main — FP8 MMA, 128x64 tile (unchanged, ~90.6 us) ----------------
#define KB 4
#define KT 64
#define PS8 144
#define QT8_BYTES (128 * PS8)
#define KT8_BYTES (KT * PS8)
#define SM_KT8    QT8_BYTES
#define SM_NRM    (QT8_BYTES + 2 * KT8_BYTES)
#define SMEM_MAIN (SM_NRM + 2 * 128 * 4 + 2 * KT * 4 + 256)

__global__ void __launch_bounds__(256, 3) k_main(float* __restrict__ out) {
    extern __shared__ char sm[];
    uint8_t* qts  = (uint8_t*)sm;
    uint8_t* kcs  = (uint8_t*)sm + SM_KT8;
    float*   qsqs = (float*)(sm + SM_NRM);
    float*   rqs  = qsqs + 128;
    float*   ksqr = rqs + 128;

    const int t = threadIdx.x;
    const int kbb = blockIdx.x, qb = blockIdx.y, b = blockIdx.z;
    const int q0 = qb * 128, kbase = kbb * (KT * KB);

    {
        const int rq = t >> 1, chb = (t & 1) * 64;
        const uint4* s1 = (const uint4*)(g_qt8 + ((size_t)(b * LQ + q0 + rq)) * DC + chb);
        #pragma unroll
        for (int i = 0; i < 4; i++) *(uint4*)(qts + rq * PS8 + chb + i * 16) = s1[i];
    }
    if (t < 128) {
        float qs = g_qsq[b * LQ + q0 + t];
        qsqs[t] = qs;
        rqs[t] = 1.f - fminf(qs, 1.f - EPSF);
    }

    const int rk = t >> 2, kchb = (t & 3) * 32;
    const int lk_ = rk & 15;
    const int prk = (rk & ~15) | (((lk_ >> 1) & 1) * 8 + ((lk_ >> 2) << 1) + (lk_ & 1));

    {
        const uint32_t dst = sptr(kcs + prk * PS8 + kchb);
        const char* src = (const char*)(g_kc8 + ((size_t)(b * LK + kbase + rk)) * DC + kchb);
        cp16(dst, src);
        cp16(dst + 16, src + 16);
        if (t < 16) cp16(sptr(&ksqr[t * 4]), g_ksq + b * LK + kbase + t * 4);
    }
    cp_commit();

    const int w = t >> 5, lane = t & 31;
    const int m0 = (w & 3) * 32, nw0 = (w >> 2) * 32;
    const int gid = lane >> 2, tid2 = lane & 3;
    const int arow = lane & 15, acolb = ((lane >> 4) << 4);
    const int brow16 = (lane & 7) + ((lane >> 4) << 3);
    const int bcolb = (((lane >> 3) & 1) << 4);

    const float N0C = EPSF + EPSF * EPSF;
    const float H0  = 0.5f * N0C;
    const float C0  = LN2F * (2.f - fast_lg2(N0C));
    const float TH  = 50.5f * N0C;
    const float I2N = 2.f * fast_rcp(N0C);

    __syncthreads();

    const int rowA0 = m0 + gid, rowA1 = m0 + 16 + gid;
    float aA[2], aB[2];
    aA[0] = qsqs[rowA0] + H0;      aB[0] = qsqs[rowA0 + 8] + H0;
    aA[1] = qsqs[rowA1] + H0;      aB[1] = qsqs[rowA1 + 8] + H0;
    bool uniQ = (aA[0] >= 1.f) & (aB[0] >= 1.f) & (aA[1] >= 1.f) & (aB[1] >= 1.f);
    float* pA0 = out + ((size_t)(b * LQ + q0 + rowA0)) * LK + kbase + nw0 + 4 * tid2;
    float* pB0 = pA0 + (size_t)8 * LK;
    float* pA1 = out + ((size_t)(b * LQ + q0 + rowA1)) * LK + kbase + nw0 + 4 * tid2;
    float* pB1 = pA1 + (size_t)8 * LK;

    for (int kb = 0; kb < KB; kb++) {
        cp_wait0();
        __syncthreads();

        const float* kraw = ksqr + (kb & 1) * KT;
        float4 ks4[2];
        ks4[0] = *(const float4*)&kraw[nw0 + 4 * tid2];
        ks4[1] = *(const float4*)&kraw[nw0 + 16 + 4 * tid2];

        if (kb + 1 < KB) {
            const int nb = (kb + 1) & 1;
            const uint32_t dst = sptr(kcs + nb * KT8_BYTES + prk * PS8 + kchb);
            const char* src = (const char*)(g_kc8 + ((size_t)(b * LK + kbase + (kb + 1) * KT + rk)) * DC + kchb);
            cp16(dst, src);
            cp16(dst + 16, src + 16);
            if (t < 16) cp16(sptr(&ksqr[nb * KT + t * 4]),
                             g_ksq + b * LK + kbase + (kb + 1) * KT + t * 4);
            cp_commit();
        }

        const uint8_t* kbuf = kcs + (kb & 1) * KT8_BYTES;

        float acc[2][4][4];
        #pragma unroll
        for (int i = 0; i < 2; i++)
            #pragma unroll
            for (int j = 0; j < 4; j++)
                #pragma unroll
                for (int c = 0; c < 4; c++) acc[i][j][c] = 0.f;

        #pragma unroll
        for (int ks = 0; ks < 4; ks++) {
            const int k0b = ks * 32;
            uint32_t A[2][4], Bf[2][4];
            #pragma unroll
            for (int ms = 0; ms < 2; ms++)
                ldsm4(A[ms][0], A[ms][1], A[ms][2], A[ms][3],
                      sptr(qts + (m0 + ms * 16 + arow) * PS8 + k0b + acolb));
            #pragma unroll
            for (int P = 0; P < 2; P++)
                ldsm4(Bf[P][0], Bf[P][1], Bf[P][2], Bf[P][3],
                      sptr(kbuf + (nw0 + P * 16 + brow16) * PS8 + k0b + bcolb));
            #pragma unroll
            for (int ms = 0; ms < 2; ms++)
                #pragma unroll
                for (int P = 0; P < 2; P++) {
                    mma16832fp8(acc[ms][2*P][0], acc[ms][2*P][1], acc[ms][2*P][2], acc[ms][2*P][3],
                                A[ms][0], A[ms][1], A[ms][2], A[ms][3], Bf[P][0], Bf[P][1]);
                    mma16832fp8(acc[ms][2*P+1][0], acc[ms][2*P+1][1], acc[ms][2*P+1][2], acc[ms][2*P+1][3],
                                A[ms][0], A[ms][1], A[ms][2], A[ms][3], Bf[P][2], Bf[P][3]);
                }
        }

        bool uni = uniQ &&
                   ks4[0].x >= 1.f - EPSF && ks4[0].y >= 1.f - EPSF &&
                   ks4[0].z >= 1.f - EPSF && ks4[0].w >= 1.f - EPSF &&
                   ks4[1].x >= 1.f - EPSF && ks4[1].y >= 1.f - EPSF &&
                   ks4[1].z >= 1.f - EPSF && ks4[1].w >= 1.f - EPSF;

        if (uni) {
            #pragma unroll
            for (int ms = 0; ms < 2; ms++) {
                float* pA = ms ? pA1 : pA0;
                float* pB = ms ? pB1 : pB0;
                #pragma unroll
                for (int P = 0; P < 2; P++) {
                    const float4 kk = ks4[P];
                    const float ksv[4] = { kk.x, kk.y, kk.z, kk.w };
                    float vA[4] = { acc[ms][2*P][0], acc[ms][2*P][1], acc[ms][2*P+1][0], acc[ms][2*P+1][1] };
                    float vB[4] = { acc[ms][2*P][2], acc[ms][2*P][3], acc[ms][2*P+1][2], acc[ms][2*P+1][3] };

                    float xA[4], xB[4], dA[4], dB[4];
                    bool bad = false;
                    #pragma unroll
                    for (int j = 0; j < 4; j++) {
                        xA[j] = fmaxf(fmaf(-2.f, vA[j], aA[ms] + ksv[j]), H0);
                        xB[j] = fmaxf(fmaf(-2.f, vB[j], aB[ms] + ksv[j]), H0);
                        bad |= (xA[j] < TH) | (xB[j] < TH);
                        dA[j] = fmaf(fast_lg2(xA[j]), LN2F, C0);
                        dB[j] = fmaf(fast_lg2(xB[j]), LN2F, C0);
                    }
                    if (bad) {
                        #pragma unroll
                        for (int j = 0; j < 4; j++) {
                            float tA = (xA[j] - H0) * I2N;
                            float sA = fast_sqrt(fmaf(tA, tA, 2.f * tA));
                            dA[j] = LN2F * fast_lg2(1.f + tA + sA);
                            float tB = (xB[j] - H0) * I2N;
                            float sB = fast_sqrt(fmaf(tB, tB, 2.f * tB));
                            dB[j] = LN2F * fast_lg2(1.f + tB + sB);
                        }
                    }
                    __stcs((float4*)(pA + P * 16), make_float4(dA[0], dA[1], dA[2], dA[3]));
                    __stcs((float4*)(pB + P * 16), make_float4(dB[0], dB[1], dB[2], dB[3]));
                }
            }
        } else {
            #pragma unroll
            for (int ms = 0; ms < 2; ms++) {
                const int rA = m0 + ms * 16 + gid, rB = rA + 8;
                const float qsA = qsqs[rA], qsB = qsqs[rB];
                const float rqA = rqs[rA],  rqB = rqs[rB];
                float* pA = ms ? pA1 : pA0;
                float* pB = ms ? pB1 : pB0;
                #pragma unroll
                for (int P = 0; P < 2; P++) {
                    const float4 kk = ks4[P];
                    const float ksv[4] = { kk.x, kk.y, kk.z, kk.w };
                    float vA[4] = { acc[ms][2*P][0], acc[ms][2*P][1], acc[ms][2*P+1][0], acc[ms][2*P+1][1] };
                    float vB[4] = { acc[ms][2*P][2], acc[ms][2*P][3], acc[ms][2*P+1][2], acc[ms][2*P+1][3] };

                    float dA[4], dB[4];
                    #pragma unroll
                    for (int j = 0; j < 4; j++) {
                        const float rkj = 1.f - fminf(ksv[j], 1.f - EPSF);
                        float uA = 2.f * fmaxf(fmaf(-2.f, vA[j], qsA + ksv[j]), 0.f);
                        float nA = fmaf(rqA, rkj, EPSF);
                        float uB = 2.f * fmaxf(fmaf(-2.f, vB[j], qsB + ksv[j]), 0.f);
                        float nB = fmaf(rqB, rkj, EPSF);
                        if (uA >= 100.f * nA) {
                            dA[j] = LN2F * (1.f + fast_lg2(uA + nA) - fast_lg2(nA));
                        } else {
                            float tA = uA * fast_rcp(nA);
                            float sA = fast_sqrt(fmaf(tA, tA, 2.f * tA));
                            dA[j] = LN2F * fast_lg2(1.f + tA + sA);
                        }
                        if (uB >= 100.f * nB) {
                            dB[j] = LN2F * (1.f + fast_lg2(uB + nB) - fast_lg2(nB));
                        } else {
                            float tB = uB * fast_rcp(nB);
                            float sB = fast_sqrt(fmaf(tB, tB, 2.f * tB));
                            dB[j] = LN2F * fast_lg2(1.f + tB + sB);
                        }
                    }
                    __stcs((float4*)(pA + P * 16), make_float4(dA[0], dA[1], dA[2], dA[3]));
                    __stcs((float4*)(pB + P * 16), make_float4(dB[0], dB[1], dB[2], dB[3]));
                }
            }
        }
        pA0 += KT; pB0 += KT; pA1 += KT; pB1 += KT;
    }
}

// ---------------- launch ----------------
extern "C" void kernel_launch(void* const* d_in, const int* in_sizes, int n_in,
                              void* d_out, int out_size) {
    const float* q   = (const float*)d_in[0];
    const int*   kq  = (const int*)d_in[1];
    const float* ksc = (const float*)d_in[2];
    const float* kz  = (const float*)d_in[3];
    const float* W   = (const float*)d_in[4];
    float* out = (float*)d_out;
    (void)in_sizes; (void)n_in; (void)out_size;

    cudaFuncSetAttribute(k_prepq, cudaFuncAttributeMaxDynamicSharedMemorySize, SMEM_PREPQ);
    cudaFuncSetAttribute(k_prepk, cudaFuncAttributeMaxDynamicSharedMemorySize, SMEM_PREPK);
    cudaFuncSetAttribute(k_main,  cudaFuncAttributeMaxDynamicSharedMemorySize, SMEM_MAIN);

    k_G<<<DC, 512>>>(W);
    k_prepq<<<(B_ * LQ) / QR, 256, SMEM_PREPQ>>>(q);
    k_prepk<<<(B_ * LK) / 128, 256, SMEM_PREPK>>>(kq, ksc, kz);
    k_main<<<dim3(LK / (KT * KB), LQ / 128, B_), 256, SMEM_MAIN>>>(out);
}